// round 3
// baseline (speedup 1.0000x reference)
#include <cuda_runtime.h>
#include <math.h>

#define TOKENS   8192
#define SEQLEN   4096
#define DMODEL   1024
#define DINNER   2048
#define NHEADS   32
#define HEADDIM  64
#define DSTATE   64
#define CHUNKL   64
#define NCHUNK   64
#define DMLP     2560
#define PROJ     9248
#define XS_OFF   2048
#define B_OFF    4096
#define C_OFF    6144
#define DT_OFF   8192
#define TH_OFF   8224

// ---------------- scratch (device globals: no allocation allowed) ----------------
__device__ float g_h[TOKENS * DMODEL];                  // rmsnorm output (reused for h2)
__device__ float g_proj[75759616];                      // TOKENS*PROJ
__device__ float g_xg[TOKENS * DINNER];                 // gamma-scaled x_ssm (reused for y_gated)
__device__ float g_Bn[TOKENS * DINNER];
__device__ float g_Cn[TOKENS * DINNER];
__device__ float g_dt[TOKENS * NHEADS];
__device__ float g_A[TOKENS * NHEADS];
__device__ float g_skip[TOKENS * NHEADS];
__device__ float g_cum[TOKENS * NHEADS * (DSTATE / 2)];
__device__ float g_states[2 * NHEADS * NCHUNK * HEADDIM * DSTATE];
__device__ float g_Bx[2 * NHEADS * NCHUNK * HEADDIM * DSTATE];
__device__ float g_rowsum[2 * NHEADS * NCHUNK * CHUNKL];
__device__ float g_expac[2 * NHEADS * NCHUNK * CHUNKL];
__device__ float g_dc[2 * NHEADS * NCHUNK];
__device__ float g_x2[TOKENS * DMODEL];
__device__ float g_gb[TOKENS * DMLP];
__device__ float g_ub[TOKENS * DMLP];

// ---------------- rmsnorm over D=1024 ----------------
__global__ __launch_bounds__(256) void rmsnorm_kernel(const float* __restrict__ x,
                                                      const float* __restrict__ w,
                                                      float* __restrict__ out) {
    int row = blockIdx.x;
    const float* xr = x + (size_t)row * DMODEL;
    float v[4];
    float s = 0.f;
#pragma unroll
    for (int i = 0; i < 4; i++) {
        v[i] = xr[threadIdx.x + i * 256];
        s += v[i] * v[i];
    }
    __shared__ float red[8];
#pragma unroll
    for (int o = 16; o; o >>= 1) s += __shfl_xor_sync(0xffffffffu, s, o);
    if ((threadIdx.x & 31) == 0) red[threadIdx.x >> 5] = s;
    __syncthreads();
    if (threadIdx.x == 0) {
        float t = 0.f;
#pragma unroll
        for (int i = 0; i < 8; i++) t += red[i];
        red[0] = rsqrtf(t / (float)DMODEL + 1e-5f);
    }
    __syncthreads();
    float r = red[0];
#pragma unroll
    for (int i = 0; i < 4; i++) {
        int c = threadIdx.x + i * 256;
        out[(size_t)row * DMODEL + c] = v[i] * r * w[c];
    }
}

// ---------------- SGEMM: C[M,N] = A[M,K] @ B[K,N] (+Res), row-major ----------------
// BM=BN=128, BK=8, 256 threads, 8x8 per thread. M%128==0, K%8==0 assumed; N guarded.
__global__ __launch_bounds__(256) void sgemm_kernel(const float* __restrict__ A,
                                                    const float* __restrict__ B,
                                                    const float* __restrict__ Res,
                                                    float* __restrict__ C,
                                                    int M, int N, int K) {
    __shared__ float As[8][128];
    __shared__ float Bs[8][128];
    int bm = blockIdx.y * 128;
    int bn = blockIdx.x * 128;
    int t = threadIdx.x;
    int tx = t & 15, ty = t >> 4;
    int arow = t >> 1, acol = (t & 1) * 4;
    int brow = t >> 5, bcol = (t & 31) * 4;

    float acc[8][8];
#pragma unroll
    for (int i = 0; i < 8; i++)
#pragma unroll
        for (int j = 0; j < 8; j++) acc[i][j] = 0.f;

    const float* Aptr = A + (size_t)(bm + arow) * K + acol;
    const float* Bptr = B + (size_t)brow * N + bn + bcol;
    bool bvalid = (bn + bcol) < N;

    for (int k0 = 0; k0 < K; k0 += 8) {
        float4 a = *(const float4*)(Aptr + k0);
        float4 bb = bvalid ? *(const float4*)(Bptr + (size_t)k0 * N)
                           : make_float4(0.f, 0.f, 0.f, 0.f);
        As[acol + 0][arow] = a.x;
        As[acol + 1][arow] = a.y;
        As[acol + 2][arow] = a.z;
        As[acol + 3][arow] = a.w;
        *(float4*)&Bs[brow][bcol] = bb;
        __syncthreads();
#pragma unroll
        for (int k = 0; k < 8; k++) {
            float am[8], bv[8];
            *(float4*)&am[0] = *(const float4*)&As[k][ty * 4];
            *(float4*)&am[4] = *(const float4*)&As[k][64 + ty * 4];
            *(float4*)&bv[0] = *(const float4*)&Bs[k][tx * 4];
            *(float4*)&bv[4] = *(const float4*)&Bs[k][64 + tx * 4];
#pragma unroll
            for (int i = 0; i < 8; i++)
#pragma unroll
                for (int j = 0; j < 8; j++) acc[i][j] += am[i] * bv[j];
        }
        __syncthreads();
    }
#pragma unroll
    for (int i = 0; i < 8; i++) {
        int r = bm + (i < 4 ? ty * 4 + i : 64 + ty * 4 + (i - 4));
#pragma unroll
        for (int j = 0; j < 8; j++) {
            int cc = bn + (j < 4 ? tx * 4 + j : 64 + tx * 4 + (j - 4));
            if (cc < N) {
                float v = acc[i][j];
                if (Res) v += Res[(size_t)r * N + cc];
                C[(size_t)r * N + cc] = v;
            }
        }
    }
}

// ---------------- per-token preprocessing ----------------
__global__ __launch_bounds__(256) void preproc_kernel(
    const float* __restrict__ proj, const float* __restrict__ A_log,
    const float* __restrict__ D_param, const float* __restrict__ dt_bias,
    const float* __restrict__ B_bias, const float* __restrict__ C_bias,
    const float* __restrict__ Bn_w, const float* __restrict__ Cn_w,
    float* __restrict__ xg, float* __restrict__ Bn, float* __restrict__ Cn,
    float* __restrict__ dtb, float* __restrict__ Ab, float* __restrict__ skipb) {
    int tok = blockIdx.x;
    const float* p = proj + (size_t)tok * PROJ;
    int warp = threadIdx.x >> 5, lane = threadIdx.x & 31;
    for (int h = warp; h < NHEADS; h += 8) {
        float xb = p[DT_OFF + h] + dt_bias[h];
        float dt = xb > 20.f ? xb : log1pf(expf(xb));
        float Av = -expf(A_log[h]) * dt;
        float alpha = expf(Av);
        float gamma = (alpha - 1.f) / (Av + 1e-6f) * 0.5f + 1.f;
        if (lane == 0) {
            dtb[tok * NHEADS + h] = dt;
            Ab[tok * NHEADS + h] = Av;
        }
        // x_ssm: skip sum (pre-gamma) + gamma-scaled copy
        float xs0 = p[XS_OFF + h * 64 + lane];
        float xs1 = p[XS_OFF + h * 64 + 32 + lane];
        float ssum = xs0 + xs1;
#pragma unroll
        for (int o = 16; o; o >>= 1) ssum += __shfl_xor_sync(0xffffffffu, ssum, o);
        if (lane == 0) skipb[tok * NHEADS + h] = D_param[h] * ssum;
        xg[(size_t)tok * DINNER + h * 64 + lane] = xs0 * gamma;
        xg[(size_t)tok * DINNER + h * 64 + 32 + lane] = xs1 * gamma;
        // B rmsnorm + bias
        float b0 = p[B_OFF + h * 64 + lane], b1 = p[B_OFF + h * 64 + 32 + lane];
        float bs = b0 * b0 + b1 * b1;
#pragma unroll
        for (int o = 16; o; o >>= 1) bs += __shfl_xor_sync(0xffffffffu, bs, o);
        float br = rsqrtf(bs / 64.f + 1e-5f);
        Bn[(size_t)tok * DINNER + h * 64 + lane] = b0 * br * Bn_w[lane] + B_bias[h * 64 + lane];
        Bn[(size_t)tok * DINNER + h * 64 + 32 + lane] =
            b1 * br * Bn_w[32 + lane] + B_bias[h * 64 + 32 + lane];
        // C rmsnorm + bias
        float c0 = p[C_OFF + h * 64 + lane], c1 = p[C_OFF + h * 64 + 32 + lane];
        float cs = c0 * c0 + c1 * c1;
#pragma unroll
        for (int o = 16; o; o >>= 1) cs += __shfl_xor_sync(0xffffffffu, cs, o);
        float cr = rsqrtf(cs / 64.f + 1e-5f);
        Cn[(size_t)tok * DINNER + h * 64 + lane] = c0 * cr * Cn_w[lane] + C_bias[h * 64 + lane];
        Cn[(size_t)tok * DINNER + h * 64 + 32 + lane] =
            c1 * cr * Cn_w[32 + lane] + C_bias[h * 64 + 32 + lane];
    }
}

// ---------------- cumsum over sequence of dt*theta: one warp per (b,h,d) ----------------
__global__ __launch_bounds__(1024) void theta_scan_kernel(const float* __restrict__ proj,
                                                          const float* __restrict__ dtb,
                                                          float* __restrict__ cum) {
    int bh = blockIdx.x;
    int b = bh >> 5, h = bh & 31;
    int d = threadIdx.x >> 5;
    int lane = threadIdx.x & 31;
    float carry = 0.f;
    for (int it = 0; it < SEQLEN / 32; it++) {
        int s = it * 32 + lane;
        int tok = b * SEQLEN + s;
        float v = dtb[tok * NHEADS + h] * proj[(size_t)tok * PROJ + TH_OFF + h * 32 + d];
#pragma unroll
        for (int o = 1; o < 32; o <<= 1) {
            float t = __shfl_up_sync(0xffffffffu, v, o);
            if (lane >= o) v += t;
        }
        v += carry;
        cum[(size_t)tok * 1024 + h * 32 + d] = v;
        carry = __shfl_sync(0xffffffffu, v, 31);
    }
}

// ---------------- RoPE on Bn, Cn (in place) ----------------
__global__ __launch_bounds__(256) void rope_kernel(const float* __restrict__ cum,
                                                   float* __restrict__ Bn,
                                                   float* __restrict__ Cn) {
    int tok = blockIdx.x;
    for (int idx = threadIdx.x; idx < 1024; idx += 256) {
        int h = idx >> 5, d = idx & 31;
        float ang = cum[(size_t)tok * 1024 + idx];
        float sn, cs;
        sincosf(ang, &sn, &cs);
        size_t base = (size_t)tok * DINNER + h * 64 + 2 * d;
        float x1 = Bn[base], x2 = Bn[base + 1];
        Bn[base] = cs * x1 - sn * x2;
        Bn[base + 1] = sn * x1 + cs * x2;
        x1 = Cn[base];
        x2 = Cn[base + 1];
        Cn[base] = cs * x1 - sn * x2;
        Cn[base + 1] = sn * x1 + cs * x2;
    }
}

// ---------------- per-chunk: states[n,p], Bx[n,p], decay scalars ----------------
__global__ __launch_bounds__(256) void ssd_chunk_kernel(
    const float* __restrict__ xg, const float* __restrict__ Bn,
    const float* __restrict__ Ab, float* __restrict__ states, float* __restrict__ Bx,
    float* __restrict__ rowsum, float* __restrict__ expac, float* __restrict__ dc) {
    int idx = blockIdx.x;                       // ((b*32+h)*64 + c)
    int c = idx & 63, h = (idx >> 6) & 31, b = idx >> 11;
    int tokbase = b * SEQLEN + c * 64;
    __shared__ float Xs[64][64];
    __shared__ float Bs[64][64];
    __shared__ float Ac[64];
    __shared__ float decs[64];
    int t = threadIdx.x;
    if (t < 64) Ac[t] = Ab[(tokbase + t) * NHEADS + h];
    __syncthreads();
    if (t == 0) {
        float s = 0.f;
        for (int l = 0; l < 64; l++) {
            s += Ac[l];
            Ac[l] = s;
        }
    }
    __syncthreads();
    float alast = Ac[63];
    if (t < 64) {
        decs[t] = expf(alast - Ac[t]);
        expac[(size_t)idx * 64 + t] = expf(Ac[t]);
        float rs = 64.f - (float)t;
        for (int s2 = 0; s2 < t; s2++) rs += expf(Ac[t] - Ac[s2]);
        rowsum[(size_t)idx * 64 + t] = rs;
    }
    if (t == 0) dc[idx] = expf(alast);
    {
        int row = t >> 2, j0 = t & 3;
        const float* xr = xg + (size_t)(tokbase + row) * DINNER + h * 64;
        const float* br = Bn + (size_t)(tokbase + row) * DINNER + h * 64;
#pragma unroll
        for (int j = j0; j < 16; j += 4) {
            *(float4*)&Xs[row][j * 4] = *(const float4*)&xr[j * 4];
            *(float4*)&Bs[row][j * 4] = *(const float4*)&br[j * 4];
        }
    }
    __syncthreads();
    int nt = (t >> 4) * 4, pt = (t & 15) * 4;
    float a1[4][4], a2[4][4];
#pragma unroll
    for (int i = 0; i < 4; i++)
#pragma unroll
        for (int j = 0; j < 4; j++) { a1[i][j] = 0.f; a2[i][j] = 0.f; }
    for (int l = 0; l < 64; l++) {
        float dv = decs[l];
        float bv[4], xv[4];
        *(float4*)bv = *(const float4*)&Bs[l][nt];
        *(float4*)xv = *(const float4*)&Xs[l][pt];
#pragma unroll
        for (int i = 0; i < 4; i++) {
            float bd = bv[i] * dv;
#pragma unroll
            for (int j = 0; j < 4; j++) {
                a1[i][j] += bv[i] * xv[j];
                a2[i][j] += bd * xv[j];
            }
        }
    }
    size_t ob = (size_t)idx * 4096;
#pragma unroll
    for (int i = 0; i < 4; i++) {
        int n = nt + i;
        *(float4*)&Bx[ob + n * 64 + pt] = make_float4(a1[i][0], a1[i][1], a1[i][2], a1[i][3]);
        *(float4*)&states[ob + n * 64 + pt] = make_float4(a2[i][0], a2[i][1], a2[i][2], a2[i][3]);
    }
}

// ---------------- inter-chunk scan (in place over states) ----------------
__global__ __launch_bounds__(256) void ssd_scan_kernel(float* __restrict__ states,
                                                       const float* __restrict__ dc) {
    int bh = blockIdx.x;
    float carry[16];
#pragma unroll
    for (int i = 0; i < 16; i++) carry[i] = 0.f;
    for (int c = 0; c < NCHUNK; c++) {
        size_t base = ((size_t)bh * 64 + c) * 4096;
        float dec = dc[bh * 64 + c];
#pragma unroll
        for (int i = 0; i < 16; i++) {
            size_t o = base + i * 256 + threadIdx.x;
            carry[i] = carry[i] * dec + states[o];
            states[o] = carry[i];
        }
    }
}

// ---------------- Y = diag(rowsum)·C·Bxᵀ + diag(expAcum)·C·Sᵀ + skip, gated by silu(z) ----------------
__global__ __launch_bounds__(256) void ssd_y_kernel(
    const float* __restrict__ Cn, const float* __restrict__ Bx,
    const float* __restrict__ states, const float* __restrict__ rowsum,
    const float* __restrict__ expac, const float* __restrict__ skipb,
    const float* __restrict__ proj, float* __restrict__ yg) {
    int idx = blockIdx.x;
    int c = idx & 63, h = (idx >> 6) & 31, b = idx >> 11;
    int tokbase = b * SEQLEN + c * 64;
    __shared__ float Ct[64][64];   // [n][l]
    __shared__ float Bxs[64][64];  // [n][p]
    __shared__ float Ss[64][64];   // [n][p]
    int t = threadIdx.x;
    size_t sb = (size_t)idx * 4096;
#pragma unroll
    for (int i = 0; i < 4; i++) {
        int e = i * 1024 + t * 4;
        *(float4*)(&Bxs[0][0] + e) = *(const float4*)&Bx[sb + e];
        *(float4*)(&Ss[0][0] + e) = *(const float4*)&states[sb + e];
    }
    {
        int row = t >> 2, j0 = t & 3;
        const float* cr = Cn + (size_t)(tokbase + row) * DINNER + h * 64;
#pragma unroll
        for (int j = j0; j < 16; j += 4) {
            float4 v = *(const float4*)&cr[j * 4];
            Ct[j * 4 + 0][row] = v.x;
            Ct[j * 4 + 1][row] = v.y;
            Ct[j * 4 + 2][row] = v.z;
            Ct[j * 4 + 3][row] = v.w;
        }
    }
    __syncthreads();
    int lt = (t >> 4) * 4, pt = (t & 15) * 4;
    float p1[4][4], p2[4][4];
#pragma unroll
    for (int i = 0; i < 4; i++)
#pragma unroll
        for (int j = 0; j < 4; j++) { p1[i][j] = 0.f; p2[i][j] = 0.f; }
    for (int n = 0; n < 64; n++) {
        float cv[4], bv[4], sv[4];
        *(float4*)cv = *(const float4*)&Ct[n][lt];
        *(float4*)bv = *(const float4*)&Bxs[n][pt];
        *(float4*)sv = *(const float4*)&Ss[n][pt];
#pragma unroll
        for (int i = 0; i < 4; i++)
#pragma unroll
            for (int j = 0; j < 4; j++) {
                p1[i][j] += cv[i] * bv[j];
                p2[i][j] += cv[i] * sv[j];
            }
    }
#pragma unroll
    for (int i = 0; i < 4; i++) {
        int l = lt + i;
        int tok = tokbase + l;
        float rs = rowsum[(size_t)idx * 64 + l];
        float ea = expac[(size_t)idx * 64 + l];
        float sk = skipb[tok * NHEADS + h];
        float4 z4 = *(const float4*)(proj + (size_t)tok * PROJ + h * 64 + pt);
        float zz[4] = {z4.x, z4.y, z4.z, z4.w};
        float o[4];
#pragma unroll
        for (int j = 0; j < 4; j++) {
            float y = rs * p1[i][j] + ea * p2[i][j] + sk;
            float z = zz[j];
            o[j] = y * (z / (1.f + expf(-z)));
        }
        *(float4*)&yg[(size_t)tok * DINNER + h * 64 + pt] = make_float4(o[0], o[1], o[2], o[3]);
    }
}

// ---------------- MLP gate: g = silu(g) * u ----------------
__global__ __launch_bounds__(256) void silumul_kernel(float* __restrict__ g,
                                                      const float* __restrict__ u, int n) {
    int i = blockIdx.x * 256 + threadIdx.x;
    if (i < n) {
        float gv = g[i];
        g[i] = gv / (1.f + expf(-gv)) * u[i];
    }
}

// ---------------- launch ----------------
extern "C" void kernel_launch(void* const* d_in, const int* in_sizes, int n_in,
                              void* d_out, int out_size) {
    (void)in_sizes; (void)n_in; (void)out_size;
    const float* x = (const float*)d_in[0];
    const float* n1w = (const float*)d_in[1];
    const float* n2w = (const float*)d_in[2];
    const float* W_in = (const float*)d_in[3];
    const float* W_out = (const float*)d_in[4];
    const float* A_log = (const float*)d_in[5];
    const float* Dp = (const float*)d_in[6];
    const float* dtbias = (const float*)d_in[7];
    const float* Bbias = (const float*)d_in[8];
    const float* Cbias = (const float*)d_in[9];
    const float* Bnw = (const float*)d_in[10];
    const float* Cnw = (const float*)d_in[11];
    const float* Wg = (const float*)d_in[12];
    const float* Wu = (const float*)d_in[13];
    const float* Wd = (const float*)d_in[14];
    float* out = (float*)d_out;

    float *h, *proj, *xg, *Bn, *Cn, *dtb, *Ab, *skipb, *cum, *states, *Bx;
    float *rowsum, *expac, *dc, *x2, *gb, *ub;
    cudaGetSymbolAddress((void**)&h, g_h);
    cudaGetSymbolAddress((void**)&proj, g_proj);
    cudaGetSymbolAddress((void**)&xg, g_xg);
    cudaGetSymbolAddress((void**)&Bn, g_Bn);
    cudaGetSymbolAddress((void**)&Cn, g_Cn);
    cudaGetSymbolAddress((void**)&dtb, g_dt);
    cudaGetSymbolAddress((void**)&Ab, g_A);
    cudaGetSymbolAddress((void**)&skipb, g_skip);
    cudaGetSymbolAddress((void**)&cum, g_cum);
    cudaGetSymbolAddress((void**)&states, g_states);
    cudaGetSymbolAddress((void**)&Bx, g_Bx);
    cudaGetSymbolAddress((void**)&rowsum, g_rowsum);
    cudaGetSymbolAddress((void**)&expac, g_expac);
    cudaGetSymbolAddress((void**)&dc, g_dc);
    cudaGetSymbolAddress((void**)&x2, g_x2);
    cudaGetSymbolAddress((void**)&gb, g_gb);
    cudaGetSymbolAddress((void**)&ub, g_ub);

    // 1) h = rmsnorm(x, norm1_w)
    rmsnorm_kernel<<<TOKENS, 256>>>(x, n1w, h);
    // 2) proj = h @ W_in   [8192 x 9248]
    sgemm_kernel<<<dim3((PROJ + 127) / 128, TOKENS / 128), 256>>>(h, W_in, nullptr, proj,
                                                                  TOKENS, PROJ, DMODEL);
    // 3) per-token preprocessing
    preproc_kernel<<<TOKENS, 256>>>(proj, A_log, Dp, dtbias, Bbias, Cbias, Bnw, Cnw, xg, Bn,
                                    Cn, dtb, Ab, skipb);
    // 4) cumtheta scan over sequence
    theta_scan_kernel<<<2 * NHEADS, 1024>>>(proj, dtb, cum);
    // 5) RoPE on B, C
    rope_kernel<<<TOKENS, 256>>>(cum, Bn, Cn);
    // 6) per-chunk states/Bx + decay scalars
    ssd_chunk_kernel<<<2 * NHEADS * NCHUNK, 256>>>(xg, Bn, Ab, states, Bx, rowsum, expac, dc);
    // 7) inter-chunk scan
    ssd_scan_kernel<<<2 * NHEADS, 256>>>(states, dc);
    // 8) Y + skip + silu(z) gate -> yg (reuses xg buffer)
    ssd_y_kernel<<<2 * NHEADS * NCHUNK, 256>>>(Cn, Bx, states, rowsum, expac, skipb, proj, xg);
    // 9) x2 = x + yg @ W_out
    sgemm_kernel<<<dim3(DMODEL / 128, TOKENS / 128), 256>>>(xg, W_out, x, x2, TOKENS, DMODEL,
                                                            DINNER);
    // 10) h2 = rmsnorm(x2) (reuse h)
    rmsnorm_kernel<<<TOKENS, 256>>>(x2, n2w, h);
    // 11/12) g = h2 @ Wg, u = h2 @ Wu
    sgemm_kernel<<<dim3(DMLP / 128, TOKENS / 128), 256>>>(h, Wg, nullptr, gb, TOKENS, DMLP,
                                                          DMODEL);
    sgemm_kernel<<<dim3(DMLP / 128, TOKENS / 128), 256>>>(h, Wu, nullptr, ub, TOKENS, DMLP,
                                                          DMODEL);
    // 13) g = silu(g) * u
    silumul_kernel<<<(TOKENS * DMLP + 255) / 256, 256>>>(gb, ub, TOKENS * DMLP);
    // 14) out = x2 + g @ Wd
    sgemm_kernel<<<dim3(DMODEL / 128, TOKENS / 128), 256>>>(gb, Wd, x2, out, TOKENS, DMODEL,
                                                            DMLP);
}

// round 4
// speedup vs baseline: 3.0409x; 3.0409x over previous
#include <cuda_runtime.h>
#include <math.h>
#include <stdint.h>

#define TOKENS   8192
#define SEQLEN   4096
#define DMODEL   1024
#define DINNER   2048
#define NHEADS   32
#define HEADDIM  64
#define DSTATE   64
#define CHUNKL   64
#define NCHUNK   64
#define DMLP     2560
#define PROJ     9248
#define XS_OFF   2048
#define B_OFF    4096
#define C_OFF    6144
#define DT_OFF   8192
#define TH_OFF   8224

// ---------------- scratch (device globals: no allocation allowed) ----------------
__device__ float g_h[TOKENS * DMODEL];
__device__ float g_proj[75759616];
__device__ float g_xg[TOKENS * DINNER];
__device__ float g_Bn[TOKENS * DINNER];
__device__ float g_Cn[TOKENS * DINNER];
__device__ float g_dt[TOKENS * NHEADS];
__device__ float g_A[TOKENS * NHEADS];
__device__ float g_skip[TOKENS * NHEADS];
__device__ float g_cum[TOKENS * NHEADS * (DSTATE / 2)];
__device__ float g_segsum[2 * NHEADS * 8 * 32];
__device__ float g_states[2 * NHEADS * NCHUNK * HEADDIM * DSTATE];
__device__ float g_Bx[2 * NHEADS * NCHUNK * HEADDIM * DSTATE];
__device__ float g_rowsum[2 * NHEADS * NCHUNK * CHUNKL];
__device__ float g_expac[2 * NHEADS * NCHUNK * CHUNKL];
__device__ float g_dc[2 * NHEADS * NCHUNK];
__device__ float g_x2[TOKENS * DMODEL];
__device__ float g_gb[TOKENS * DMLP];
__device__ float g_ub[TOKENS * DMLP];
// tf32-rounded weight copies
__device__ float g_Winr[DMODEL * PROJ];
__device__ float g_Woutr[DINNER * DMODEL];
__device__ float g_Wgr[DMODEL * DMLP];
__device__ float g_Wur[DMODEL * DMLP];
__device__ float g_Wdr[DMLP * DMODEL];

// ---------------- helpers ----------------
__device__ __forceinline__ float rtf(float x) {
    uint32_t o;
    asm("cvt.rna.tf32.f32 %0, %1;" : "=r"(o) : "f"(x));
    return __uint_as_float(o);
}

__device__ __forceinline__ void cp16(void* smem, const void* g) {
    uint32_t s = (uint32_t)__cvta_generic_to_shared(smem);
    asm volatile("cp.async.cg.shared.global [%0], [%1], 16;" ::"r"(s), "l"(g));
}

__device__ __forceinline__ void mma_tf32(float* c, const uint32_t* a, const uint32_t* b) {
    asm volatile(
        "mma.sync.aligned.m16n8k8.row.col.f32.tf32.tf32.f32 "
        "{%0,%1,%2,%3},{%4,%5,%6,%7},{%8,%9},{%0,%1,%2,%3};"
        : "+f"(c[0]), "+f"(c[1]), "+f"(c[2]), "+f"(c[3])
        : "r"(a[0]), "r"(a[1]), "r"(a[2]), "r"(a[3]), "r"(b[0]), "r"(b[1]));
}

// ---------------- elementwise tf32 rounding (for weights) ----------------
__global__ __launch_bounds__(256) void round_kernel(float* __restrict__ dst,
                                                    const float* __restrict__ src, int n4) {
    int i = blockIdx.x * 256 + threadIdx.x;
    if (i < n4) {
        float4 v = ((const float4*)src)[i];
        v.x = rtf(v.x); v.y = rtf(v.y); v.z = rtf(v.z); v.w = rtf(v.w);
        ((float4*)dst)[i] = v;
    }
}

// ---------------- rmsnorm over D=1024 (output tf32-rounded) ----------------
__global__ __launch_bounds__(256) void rmsnorm_kernel(const float* __restrict__ x,
                                                      const float* __restrict__ w,
                                                      float* __restrict__ out) {
    int row = blockIdx.x;
    const float* xr = x + (size_t)row * DMODEL;
    float v[4];
    float s = 0.f;
#pragma unroll
    for (int i = 0; i < 4; i++) {
        v[i] = xr[threadIdx.x + i * 256];
        s += v[i] * v[i];
    }
    __shared__ float red[8];
#pragma unroll
    for (int o = 16; o; o >>= 1) s += __shfl_xor_sync(0xffffffffu, s, o);
    if ((threadIdx.x & 31) == 0) red[threadIdx.x >> 5] = s;
    __syncthreads();
    if (threadIdx.x == 0) {
        float t = 0.f;
#pragma unroll
        for (int i = 0; i < 8; i++) t += red[i];
        red[0] = rsqrtf(t / (float)DMODEL + 1e-5f);
    }
    __syncthreads();
    float r = red[0];
#pragma unroll
    for (int i = 0; i < 4; i++) {
        int c = threadIdx.x + i * 256;
        out[(size_t)row * DMODEL + c] = rtf(v[i] * r * w[c]);
    }
}

// ---------------- TF32 tensor-core GEMM: C[M,N] = A[M,K]@B[K,N] (+Res) ----------------
// BM=128 BN=128 BK=16, 256 threads, warp grid 2(M)x4(N), warp tile 64x32.
// Inputs assumed pre-rounded to tf32. M%128==0, K%16==0; N%32==0 (edge guarded).
__global__ __launch_bounds__(256, 2) void tgemm_kernel(const float* __restrict__ A,
                                                       const float* __restrict__ B,
                                                       const float* __restrict__ Res,
                                                       float* __restrict__ C,
                                                       int M, int N, int K) {
    __shared__ float As[2][128][20];   // [m][k], stride 20 -> conflict-free frags
    __shared__ float Bs[2][16][136];   // [k][n], stride 136 -> conflict-free frags
    int bm = blockIdx.y * 128, bn = blockIdx.x * 128;
    int t = threadIdx.x;
    int warp = t >> 5, lane = t & 31;
    int wm = warp & 1, wn = warp >> 1;
    int g = lane >> 2, tg = lane & 3;

    int ar0 = t >> 2, ac0 = (t & 3) * 4;   // A: 2 float4 per thread (rows ar0, ar0+64)
    int br0 = t >> 5, bc0 = (t & 31) * 4;  // B: 2 float4 per thread (rows br0, br0+8)
    bool bok = (bn + bc0) < N;

    float acc[4][4][4];
#pragma unroll
    for (int mi = 0; mi < 4; mi++)
#pragma unroll
        for (int ni = 0; ni < 4; ni++)
#pragma unroll
            for (int j = 0; j < 4; j++) acc[mi][ni][j] = 0.f;

    auto issue = [&](int buf, int k0) {
        cp16(&As[buf][ar0][ac0], A + (size_t)(bm + ar0) * K + k0 + ac0);
        cp16(&As[buf][ar0 + 64][ac0], A + (size_t)(bm + ar0 + 64) * K + k0 + ac0);
        if (bok) {
            cp16(&Bs[buf][br0][bc0], B + (size_t)(k0 + br0) * N + bn + bc0);
            cp16(&Bs[buf][br0 + 8][bc0], B + (size_t)(k0 + br0 + 8) * N + bn + bc0);
        } else {
            float4 z = make_float4(0.f, 0.f, 0.f, 0.f);
            *(float4*)&Bs[buf][br0][bc0] = z;
            *(float4*)&Bs[buf][br0 + 8][bc0] = z;
        }
        asm volatile("cp.async.commit_group;");
    };

    int nk = K / 16;
    issue(0, 0);
    for (int it = 0; it < nk; it++) {
        int buf = it & 1;
        if (it + 1 < nk) {
            issue(buf ^ 1, (it + 1) * 16);
            asm volatile("cp.async.wait_group 1;");
        } else {
            asm volatile("cp.async.wait_group 0;");
        }
        __syncthreads();
        const float(*as)[20] = As[buf];
        const float(*bs)[136] = Bs[buf];
#pragma unroll
        for (int kk = 0; kk < 16; kk += 8) {
            uint32_t af[4][4], bf[4][2];
#pragma unroll
            for (int mi = 0; mi < 4; mi++) {
                int r = wm * 64 + mi * 16 + g;
                af[mi][0] = __float_as_uint(as[r][kk + tg]);
                af[mi][1] = __float_as_uint(as[r + 8][kk + tg]);
                af[mi][2] = __float_as_uint(as[r][kk + tg + 4]);
                af[mi][3] = __float_as_uint(as[r + 8][kk + tg + 4]);
            }
#pragma unroll
            for (int ni = 0; ni < 4; ni++) {
                int n0 = wn * 32 + ni * 8 + g;
                bf[ni][0] = __float_as_uint(bs[kk + tg][n0]);
                bf[ni][1] = __float_as_uint(bs[kk + tg + 4][n0]);
            }
#pragma unroll
            for (int mi = 0; mi < 4; mi++)
#pragma unroll
                for (int ni = 0; ni < 4; ni++) mma_tf32(acc[mi][ni], af[mi], bf[ni]);
        }
        __syncthreads();
    }

#pragma unroll
    for (int mi = 0; mi < 4; mi++) {
        int r0 = bm + wm * 64 + mi * 16 + g;
#pragma unroll
        for (int ni = 0; ni < 4; ni++) {
            int c0 = bn + wn * 32 + ni * 8 + 2 * tg;
            if (c0 < N) {
                float v0 = acc[mi][ni][0], v1 = acc[mi][ni][1];
                float v2 = acc[mi][ni][2], v3 = acc[mi][ni][3];
                if (Res) {
                    v0 += Res[(size_t)r0 * N + c0];
                    v1 += Res[(size_t)r0 * N + c0 + 1];
                    v2 += Res[(size_t)(r0 + 8) * N + c0];
                    v3 += Res[(size_t)(r0 + 8) * N + c0 + 1];
                }
                *(float2*)&C[(size_t)r0 * N + c0] = make_float2(v0, v1);
                *(float2*)&C[(size_t)(r0 + 8) * N + c0] = make_float2(v2, v3);
            }
        }
    }
}

// ---------------- per-token preprocessing ----------------
__global__ __launch_bounds__(256) void preproc_kernel(
    const float* __restrict__ proj, const float* __restrict__ A_log,
    const float* __restrict__ D_param, const float* __restrict__ dt_bias,
    const float* __restrict__ B_bias, const float* __restrict__ C_bias,
    const float* __restrict__ Bn_w, const float* __restrict__ Cn_w,
    float* __restrict__ xg, float* __restrict__ Bn, float* __restrict__ Cn,
    float* __restrict__ dtb, float* __restrict__ Ab, float* __restrict__ skipb) {
    int tok = blockIdx.x;
    const float* p = proj + (size_t)tok * PROJ;
    int warp = threadIdx.x >> 5, lane = threadIdx.x & 31;
    for (int h = warp; h < NHEADS; h += 8) {
        float xb = p[DT_OFF + h] + dt_bias[h];
        float dt = xb > 20.f ? xb : log1pf(expf(xb));
        float Av = -expf(A_log[h]) * dt;
        float alpha = expf(Av);
        float gamma = (alpha - 1.f) / (Av + 1e-6f) * 0.5f + 1.f;
        if (lane == 0) {
            dtb[tok * NHEADS + h] = dt;
            Ab[tok * NHEADS + h] = Av;
        }
        float xs0 = p[XS_OFF + h * 64 + lane];
        float xs1 = p[XS_OFF + h * 64 + 32 + lane];
        float ssum = xs0 + xs1;
#pragma unroll
        for (int o = 16; o; o >>= 1) ssum += __shfl_xor_sync(0xffffffffu, ssum, o);
        if (lane == 0) skipb[tok * NHEADS + h] = D_param[h] * ssum;
        xg[(size_t)tok * DINNER + h * 64 + lane] = xs0 * gamma;
        xg[(size_t)tok * DINNER + h * 64 + 32 + lane] = xs1 * gamma;
        float b0 = p[B_OFF + h * 64 + lane], b1 = p[B_OFF + h * 64 + 32 + lane];
        float bs = b0 * b0 + b1 * b1;
#pragma unroll
        for (int o = 16; o; o >>= 1) bs += __shfl_xor_sync(0xffffffffu, bs, o);
        float br = rsqrtf(bs / 64.f + 1e-5f);
        Bn[(size_t)tok * DINNER + h * 64 + lane] = b0 * br * Bn_w[lane] + B_bias[h * 64 + lane];
        Bn[(size_t)tok * DINNER + h * 64 + 32 + lane] =
            b1 * br * Bn_w[32 + lane] + B_bias[h * 64 + 32 + lane];
        float c0 = p[C_OFF + h * 64 + lane], c1 = p[C_OFF + h * 64 + 32 + lane];
        float cs = c0 * c0 + c1 * c1;
#pragma unroll
        for (int o = 16; o; o >>= 1) cs += __shfl_xor_sync(0xffffffffu, cs, o);
        float cr = rsqrtf(cs / 64.f + 1e-5f);
        Cn[(size_t)tok * DINNER + h * 64 + lane] = c0 * cr * Cn_w[lane] + C_bias[h * 64 + lane];
        Cn[(size_t)tok * DINNER + h * 64 + 32 + lane] =
            c1 * cr * Cn_w[32 + lane] + C_bias[h * 64 + 32 + lane];
    }
}

// ---------------- theta cumsum, two-pass segmented scan ----------------
// pass 1: 512 blocks = (b,h,seg of 512 tokens); block 1024 = 32 warps x 32 lanes
__global__ __launch_bounds__(1024) void theta_scan1(const float* __restrict__ proj,
                                                    const float* __restrict__ dtb,
                                                    float* __restrict__ cum,
                                                    float* __restrict__ segsum) {
    int blk = blockIdx.x;
    int seg = blk & 7, h = (blk >> 3) & 31, b = blk >> 8;
    int w = threadIdx.x >> 5, lane = threadIdx.x & 31;
    __shared__ float T[32][33];
    __shared__ float O[32][33];
    __shared__ float Dt[32];
    int s0 = b * SEQLEN + seg * 512;
    float carry = 0.f;
    for (int it = 0; it < 16; it++) {
        int tk = s0 + it * 32;
        T[w][lane] = proj[(size_t)(tk + w) * PROJ + TH_OFF + h * 32 + lane];  // coalesced
        if (w == 0) Dt[lane] = dtb[(tk + lane) * NHEADS + h];
        __syncthreads();
        // thread handles d=w, seq position=lane
        float v = Dt[lane] * T[lane][w];
#pragma unroll
        for (int o = 1; o < 32; o <<= 1) {
            float tv = __shfl_up_sync(0xffffffffu, v, o);
            if (lane >= o) v += tv;
        }
        v += carry;
        float cnew = __shfl_sync(0xffffffffu, v, 31);
        O[lane][w] = v;
        __syncthreads();
        cum[(size_t)(tk + w) * 1024 + h * 32 + lane] = O[w][lane];  // coalesced
        carry = cnew;
    }
    if (lane == 0) segsum[blk * 32 + w] = carry;
}
// pass 2: add exclusive segment offsets
__global__ __launch_bounds__(1024) void theta_scan2(float* __restrict__ cum,
                                                    const float* __restrict__ segsum) {
    int blk = blockIdx.x;
    int seg = blk & 7;
    if (seg == 0) return;
    int h = (blk >> 3) & 31, b = blk >> 8;
    int w = threadIdx.x >> 5, lane = threadIdx.x & 31;
    int bh8 = ((b * 32 + h) * 8);
    float off = 0.f;
    for (int s = 0; s < seg; s++) off += segsum[(bh8 + s) * 32 + lane];
    int s0 = b * SEQLEN + seg * 512;
    for (int it = 0; it < 16; it++) {
        int tok = s0 + it * 32 + w;
        cum[(size_t)tok * 1024 + h * 32 + lane] += off;
    }
}

// ---------------- RoPE on Bn, Cn (in place) ----------------
__global__ __launch_bounds__(256) void rope_kernel(const float* __restrict__ cum,
                                                   float* __restrict__ Bn,
                                                   float* __restrict__ Cn) {
    int tok = blockIdx.x;
    for (int idx = threadIdx.x; idx < 1024; idx += 256) {
        int h = idx >> 5, d = idx & 31;
        float ang = cum[(size_t)tok * 1024 + idx];
        float sn, cs;
        __sincosf(ang, &sn, &cs);
        size_t base = (size_t)tok * DINNER + h * 64 + 2 * d;
        float x1 = Bn[base], x2 = Bn[base + 1];
        Bn[base] = cs * x1 - sn * x2;
        Bn[base + 1] = sn * x1 + cs * x2;
        x1 = Cn[base];
        x2 = Cn[base + 1];
        Cn[base] = cs * x1 - sn * x2;
        Cn[base + 1] = sn * x1 + cs * x2;
    }
}

// ---------------- per-chunk: states[n,p], Bx[n,p], decay scalars ----------------
__global__ __launch_bounds__(256) void ssd_chunk_kernel(
    const float* __restrict__ xg, const float* __restrict__ Bn,
    const float* __restrict__ Ab, float* __restrict__ states, float* __restrict__ Bx,
    float* __restrict__ rowsum, float* __restrict__ expac, float* __restrict__ dc) {
    int idx = blockIdx.x;
    int c = idx & 63, h = (idx >> 6) & 31, b = idx >> 11;
    int tokbase = b * SEQLEN + c * 64;
    __shared__ float Xs[64][64];
    __shared__ float Bs[64][64];
    __shared__ float Ac[64];
    __shared__ float decs[64];
    int t = threadIdx.x;
    if (t < 64) Ac[t] = Ab[(tokbase + t) * NHEADS + h];
    __syncthreads();
    if (t == 0) {
        float s = 0.f;
        for (int l = 0; l < 64; l++) {
            s += Ac[l];
            Ac[l] = s;
        }
    }
    __syncthreads();
    float alast = Ac[63];
    if (t < 64) {
        decs[t] = expf(alast - Ac[t]);
        expac[(size_t)idx * 64 + t] = expf(Ac[t]);
        float rs = 64.f - (float)t;
        for (int s2 = 0; s2 < t; s2++) rs += expf(Ac[t] - Ac[s2]);
        rowsum[(size_t)idx * 64 + t] = rs;
    }
    if (t == 0) dc[idx] = expf(alast);
    {
        int row = t >> 2, j0 = t & 3;
        const float* xr = xg + (size_t)(tokbase + row) * DINNER + h * 64;
        const float* br = Bn + (size_t)(tokbase + row) * DINNER + h * 64;
#pragma unroll
        for (int j = j0; j < 16; j += 4) {
            *(float4*)&Xs[row][j * 4] = *(const float4*)&xr[j * 4];
            *(float4*)&Bs[row][j * 4] = *(const float4*)&br[j * 4];
        }
    }
    __syncthreads();
    int nt = (t >> 4) * 4, pt = (t & 15) * 4;
    float a1[4][4], a2[4][4];
#pragma unroll
    for (int i = 0; i < 4; i++)
#pragma unroll
        for (int j = 0; j < 4; j++) { a1[i][j] = 0.f; a2[i][j] = 0.f; }
    for (int l = 0; l < 64; l++) {
        float dv = decs[l];
        float bv[4], xv[4];
        *(float4*)bv = *(const float4*)&Bs[l][nt];
        *(float4*)xv = *(const float4*)&Xs[l][pt];
#pragma unroll
        for (int i = 0; i < 4; i++) {
            float bd = bv[i] * dv;
#pragma unroll
            for (int j = 0; j < 4; j++) {
                a1[i][j] += bv[i] * xv[j];
                a2[i][j] += bd * xv[j];
            }
        }
    }
    size_t ob = (size_t)idx * 4096;
#pragma unroll
    for (int i = 0; i < 4; i++) {
        int n = nt + i;
        *(float4*)&Bx[ob + n * 64 + pt] = make_float4(a1[i][0], a1[i][1], a1[i][2], a1[i][3]);
        *(float4*)&states[ob + n * 64 + pt] = make_float4(a2[i][0], a2[i][1], a2[i][2], a2[i][3]);
    }
}

// ---------------- inter-chunk scan (in place over states) ----------------
__global__ __launch_bounds__(256) void ssd_scan_kernel(float* __restrict__ states,
                                                       const float* __restrict__ dc) {
    int bh = blockIdx.x;
    float carry[16];
#pragma unroll
    for (int i = 0; i < 16; i++) carry[i] = 0.f;
    for (int c = 0; c < NCHUNK; c++) {
        size_t base = ((size_t)bh * 64 + c) * 4096;
        float dec = dc[bh * 64 + c];
#pragma unroll
        for (int i = 0; i < 16; i++) {
            size_t o = base + i * 256 + threadIdx.x;
            carry[i] = carry[i] * dec + states[o];
            states[o] = carry[i];
        }
    }
}

// ---------------- Y + skip, gated by silu(z) -> yg (tf32-rounded for next GEMM) --------
__global__ __launch_bounds__(256) void ssd_y_kernel(
    const float* __restrict__ Cn, const float* __restrict__ Bx,
    const float* __restrict__ states, const float* __restrict__ rowsum,
    const float* __restrict__ expac, const float* __restrict__ skipb,
    const float* __restrict__ proj, float* __restrict__ yg) {
    int idx = blockIdx.x;
    int c = idx & 63, h = (idx >> 6) & 31, b = idx >> 11;
    int tokbase = b * SEQLEN + c * 64;
    __shared__ float Ct[64][64];
    __shared__ float Bxs[64][64];
    __shared__ float Ss[64][64];
    int t = threadIdx.x;
    size_t sb = (size_t)idx * 4096;
#pragma unroll
    for (int i = 0; i < 4; i++) {
        int e = i * 1024 + t * 4;
        *(float4*)(&Bxs[0][0] + e) = *(const float4*)&Bx[sb + e];
        *(float4*)(&Ss[0][0] + e) = *(const float4*)&states[sb + e];
    }
    {
        int row = t >> 2, j0 = t & 3;
        const float* cr = Cn + (size_t)(tokbase + row) * DINNER + h * 64;
#pragma unroll
        for (int j = j0; j < 16; j += 4) {
            float4 v = *(const float4*)&cr[j * 4];
            Ct[j * 4 + 0][row] = v.x;
            Ct[j * 4 + 1][row] = v.y;
            Ct[j * 4 + 2][row] = v.z;
            Ct[j * 4 + 3][row] = v.w;
        }
    }
    __syncthreads();
    int lt = (t >> 4) * 4, pt = (t & 15) * 4;
    float p1[4][4], p2[4][4];
#pragma unroll
    for (int i = 0; i < 4; i++)
#pragma unroll
        for (int j = 0; j < 4; j++) { p1[i][j] = 0.f; p2[i][j] = 0.f; }
    for (int n = 0; n < 64; n++) {
        float cv[4], bv[4], sv[4];
        *(float4*)cv = *(const float4*)&Ct[n][lt];
        *(float4*)bv = *(const float4*)&Bxs[n][pt];
        *(float4*)sv = *(const float4*)&Ss[n][pt];
#pragma unroll
        for (int i = 0; i < 4; i++)
#pragma unroll
            for (int j = 0; j < 4; j++) {
                p1[i][j] += cv[i] * bv[j];
                p2[i][j] += cv[i] * sv[j];
            }
    }
#pragma unroll
    for (int i = 0; i < 4; i++) {
        int l = lt + i;
        int tok = tokbase + l;
        float rs = rowsum[(size_t)idx * 64 + l];
        float ea = expac[(size_t)idx * 64 + l];
        float sk = skipb[tok * NHEADS + h];
        float4 z4 = *(const float4*)(proj + (size_t)tok * PROJ + h * 64 + pt);
        float zz[4] = {z4.x, z4.y, z4.z, z4.w};
        float o[4];
#pragma unroll
        for (int j = 0; j < 4; j++) {
            float y = rs * p1[i][j] + ea * p2[i][j] + sk;
            float z = zz[j];
            o[j] = rtf(y * (z / (1.f + expf(-z))));
        }
        *(float4*)&yg[(size_t)tok * DINNER + h * 64 + pt] = make_float4(o[0], o[1], o[2], o[3]);
    }
}

// ---------------- MLP gate: g = silu(g) * u (tf32-rounded) ----------------
__global__ __launch_bounds__(256) void silumul_kernel(float* __restrict__ g,
                                                      const float* __restrict__ u, int n) {
    int i = blockIdx.x * 256 + threadIdx.x;
    if (i < n) {
        float gv = g[i];
        g[i] = rtf(gv / (1.f + expf(-gv)) * u[i]);
    }
}

// ---------------- launch ----------------
extern "C" void kernel_launch(void* const* d_in, const int* in_sizes, int n_in,
                              void* d_out, int out_size) {
    (void)in_sizes; (void)n_in; (void)out_size;
    const float* x = (const float*)d_in[0];
    const float* n1w = (const float*)d_in[1];
    const float* n2w = (const float*)d_in[2];
    const float* W_in = (const float*)d_in[3];
    const float* W_out = (const float*)d_in[4];
    const float* A_log = (const float*)d_in[5];
    const float* Dp = (const float*)d_in[6];
    const float* dtbias = (const float*)d_in[7];
    const float* Bbias = (const float*)d_in[8];
    const float* Cbias = (const float*)d_in[9];
    const float* Bnw = (const float*)d_in[10];
    const float* Cnw = (const float*)d_in[11];
    const float* Wg = (const float*)d_in[12];
    const float* Wu = (const float*)d_in[13];
    const float* Wd = (const float*)d_in[14];
    float* out = (float*)d_out;

    float *h, *proj, *xg, *Bn, *Cn, *dtb, *Ab, *skipb, *cum, *segsum, *states, *Bx;
    float *rowsum, *expac, *dc, *x2, *gb, *ub;
    float *winr, *woutr, *wgr, *wur, *wdr;
    cudaGetSymbolAddress((void**)&h, g_h);
    cudaGetSymbolAddress((void**)&proj, g_proj);
    cudaGetSymbolAddress((void**)&xg, g_xg);
    cudaGetSymbolAddress((void**)&Bn, g_Bn);
    cudaGetSymbolAddress((void**)&Cn, g_Cn);
    cudaGetSymbolAddress((void**)&dtb, g_dt);
    cudaGetSymbolAddress((void**)&Ab, g_A);
    cudaGetSymbolAddress((void**)&skipb, g_skip);
    cudaGetSymbolAddress((void**)&cum, g_cum);
    cudaGetSymbolAddress((void**)&segsum, g_segsum);
    cudaGetSymbolAddress((void**)&states, g_states);
    cudaGetSymbolAddress((void**)&Bx, g_Bx);
    cudaGetSymbolAddress((void**)&rowsum, g_rowsum);
    cudaGetSymbolAddress((void**)&expac, g_expac);
    cudaGetSymbolAddress((void**)&dc, g_dc);
    cudaGetSymbolAddress((void**)&x2, g_x2);
    cudaGetSymbolAddress((void**)&gb, g_gb);
    cudaGetSymbolAddress((void**)&ub, g_ub);
    cudaGetSymbolAddress((void**)&winr, g_Winr);
    cudaGetSymbolAddress((void**)&woutr, g_Woutr);
    cudaGetSymbolAddress((void**)&wgr, g_Wgr);
    cudaGetSymbolAddress((void**)&wur, g_Wur);
    cudaGetSymbolAddress((void**)&wdr, g_Wdr);

    // 0) round weights to nearest-tf32 once per call
    round_kernel<<<(DMODEL * PROJ / 4 + 255) / 256, 256>>>(winr, W_in, DMODEL * PROJ / 4);
    round_kernel<<<(DINNER * DMODEL / 4 + 255) / 256, 256>>>(woutr, W_out, DINNER * DMODEL / 4);
    round_kernel<<<(DMODEL * DMLP / 4 + 255) / 256, 256>>>(wgr, Wg, DMODEL * DMLP / 4);
    round_kernel<<<(DMODEL * DMLP / 4 + 255) / 256, 256>>>(wur, Wu, DMODEL * DMLP / 4);
    round_kernel<<<(DMLP * DMODEL / 4 + 255) / 256, 256>>>(wdr, Wd, DMLP * DMODEL / 4);

    // 1) h = rmsnorm(x) (tf32-rounded)
    rmsnorm_kernel<<<TOKENS, 256>>>(x, n1w, h);
    // 2) proj = h @ W_in
    tgemm_kernel<<<dim3((PROJ + 127) / 128, TOKENS / 128), 256>>>(h, winr, nullptr, proj,
                                                                  TOKENS, PROJ, DMODEL);
    // 3) per-token preprocessing
    preproc_kernel<<<TOKENS, 256>>>(proj, A_log, Dp, dtbias, Bbias, Cbias, Bnw, Cnw, xg, Bn,
                                    Cn, dtb, Ab, skipb);
    // 4) cumtheta segmented scan
    theta_scan1<<<2 * NHEADS * 8, 1024>>>(proj, dtb, cum, segsum);
    theta_scan2<<<2 * NHEADS * 8, 1024>>>(cum, segsum);
    // 5) RoPE
    rope_kernel<<<TOKENS, 256>>>(cum, Bn, Cn);
    // 6) per-chunk states/Bx + decay scalars
    ssd_chunk_kernel<<<2 * NHEADS * NCHUNK, 256>>>(xg, Bn, Ab, states, Bx, rowsum, expac, dc);
    // 7) inter-chunk scan
    ssd_scan_kernel<<<2 * NHEADS, 256>>>(states, dc);
    // 8) Y + skip + silu(z) gate -> yg (reuses xg)
    ssd_y_kernel<<<2 * NHEADS * NCHUNK, 256>>>(Cn, Bx, states, rowsum, expac, skipb, proj, xg);
    // 9) x2 = x + yg @ W_out
    tgemm_kernel<<<dim3(DMODEL / 128, TOKENS / 128), 256>>>(xg, woutr, x, x2, TOKENS, DMODEL,
                                                            DINNER);
    // 10) h2 = rmsnorm(x2)
    rmsnorm_kernel<<<TOKENS, 256>>>(x2, n2w, h);
    // 11/12) g = h2 @ Wg, u = h2 @ Wu
    tgemm_kernel<<<dim3(DMLP / 128, TOKENS / 128), 256>>>(h, wgr, nullptr, gb, TOKENS, DMLP,
                                                          DMODEL);
    tgemm_kernel<<<dim3(DMLP / 128, TOKENS / 128), 256>>>(h, wur, nullptr, ub, TOKENS, DMLP,
                                                          DMODEL);
    // 13) g = silu(g) * u
    silumul_kernel<<<(TOKENS * DMLP + 255) / 256, 256>>>(gb, ub, TOKENS * DMLP);
    // 14) out = x2 + g @ Wd
    tgemm_kernel<<<dim3(DMODEL / 128, TOKENS / 128), 256>>>(gb, wdr, x2, out, TOKENS, DMODEL,
                                                            DMLP);
}

// round 5
// speedup vs baseline: 3.0956x; 1.0180x over previous
#include <cuda_runtime.h>
#include <math.h>
#include <stdint.h>

#define TOKENS   8192
#define SEQLEN   4096
#define DMODEL   1024
#define DINNER   2048
#define NHEADS   32
#define HEADDIM  64
#define DSTATE   64
#define CHUNKL   64
#define NCHUNK   64
#define DMLP     2560
#define PROJ     9248
#define XS_OFF   2048
#define B_OFF    4096
#define C_OFF    6144
#define DT_OFF   8192
#define TH_OFF   8224

// ---------------- scratch (device globals: no allocation allowed) ----------------
__device__ float g_h[TOKENS * DMODEL];
__device__ float g_proj[75759616];
__device__ float g_xg[TOKENS * DINNER];
__device__ float g_Bn[TOKENS * DINNER];
__device__ float g_Cn[TOKENS * DINNER];
__device__ float g_dt[TOKENS * NHEADS];
__device__ float g_A[TOKENS * NHEADS];
__device__ float g_skip[TOKENS * NHEADS];
__device__ float g_cum[TOKENS * NHEADS * (DSTATE / 2)];
__device__ float g_segsum[2 * NHEADS * 8 * 32];
__device__ float g_states[2 * NHEADS * NCHUNK * HEADDIM * DSTATE];
__device__ float g_Bx[2 * NHEADS * NCHUNK * HEADDIM * DSTATE];
__device__ float g_rowsum[2 * NHEADS * NCHUNK * CHUNKL];
__device__ float g_expac[2 * NHEADS * NCHUNK * CHUNKL];
__device__ float g_dc[2 * NHEADS * NCHUNK];
__device__ float g_x2[TOKENS * DMODEL];
__device__ float g_gb[TOKENS * DMLP];
__device__ float g_ub[TOKENS * DMLP];
// tf32-rounded weight copies
__device__ float g_Winr[DMODEL * PROJ];
__device__ float g_Woutr[DINNER * DMODEL];
__device__ float g_Wgr[DMODEL * DMLP];
__device__ float g_Wur[DMODEL * DMLP];
__device__ float g_Wdr[DMLP * DMODEL];

// ---------------- helpers ----------------
__device__ __forceinline__ float rtf(float x) {
    uint32_t o;
    asm("cvt.rna.tf32.f32 %0, %1;" : "=r"(o) : "f"(x));
    return __uint_as_float(o);
}

__device__ __forceinline__ void cp16(void* smem, const void* g) {
    uint32_t s = (uint32_t)__cvta_generic_to_shared(smem);
    asm volatile("cp.async.cg.shared.global [%0], [%1], 16;" ::"r"(s), "l"(g));
}

__device__ __forceinline__ void mma_tf32(float* c, const uint32_t* a, const uint32_t* b) {
    asm volatile(
        "mma.sync.aligned.m16n8k8.row.col.f32.tf32.tf32.f32 "
        "{%0,%1,%2,%3},{%4,%5,%6,%7},{%8,%9},{%0,%1,%2,%3};"
        : "+f"(c[0]), "+f"(c[1]), "+f"(c[2]), "+f"(c[3])
        : "r"(a[0]), "r"(a[1]), "r"(a[2]), "r"(a[3]), "r"(b[0]), "r"(b[1]));
}

// ---------------- combined tf32 rounding of all 5 weights (one launch) ----------------
#define R0N 2367488            // W_in  / 4
#define R1N 524288             // W_out / 4
#define R2N 655360             // Wg    / 4
#define R3N 655360             // Wu    / 4
#define R4N 655360             // Wd    / 4
#define RTOT (R0N + R1N + R2N + R3N + R4N)
__global__ __launch_bounds__(256) void round_all_kernel(
    float* __restrict__ d0, const float* __restrict__ s0, float* __restrict__ d1,
    const float* __restrict__ s1, float* __restrict__ d2, const float* __restrict__ s2,
    float* __restrict__ d3, const float* __restrict__ s3, float* __restrict__ d4,
    const float* __restrict__ s4) {
    int i = blockIdx.x * 256 + threadIdx.x;
    if (i >= RTOT) return;
    const float4* src;
    float4* dst;
    int j = i;
    if (j < R0N) { src = (const float4*)s0; dst = (float4*)d0; }
    else if ((j -= R0N) < R1N) { src = (const float4*)s1; dst = (float4*)d1; }
    else if ((j -= R1N) < R2N) { src = (const float4*)s2; dst = (float4*)d2; }
    else if ((j -= R2N) < R3N) { src = (const float4*)s3; dst = (float4*)d3; }
    else { j -= R3N; src = (const float4*)s4; dst = (float4*)d4; }
    float4 v = src[j];
    v.x = rtf(v.x); v.y = rtf(v.y); v.z = rtf(v.z); v.w = rtf(v.w);
    dst[j] = v;
}

// ---------------- rmsnorm over D=1024 (output tf32-rounded) ----------------
__global__ __launch_bounds__(256) void rmsnorm_kernel(const float* __restrict__ x,
                                                      const float* __restrict__ w,
                                                      float* __restrict__ out) {
    int row = blockIdx.x;
    const float* xr = x + (size_t)row * DMODEL;
    float v[4];
    float s = 0.f;
#pragma unroll
    for (int i = 0; i < 4; i++) {
        v[i] = xr[threadIdx.x + i * 256];
        s += v[i] * v[i];
    }
    __shared__ float red[8];
#pragma unroll
    for (int o = 16; o; o >>= 1) s += __shfl_xor_sync(0xffffffffu, s, o);
    if ((threadIdx.x & 31) == 0) red[threadIdx.x >> 5] = s;
    __syncthreads();
    if (threadIdx.x == 0) {
        float t = 0.f;
#pragma unroll
        for (int i = 0; i < 8; i++) t += red[i];
        red[0] = rsqrtf(t / (float)DMODEL + 1e-5f);
    }
    __syncthreads();
    float r = red[0];
#pragma unroll
    for (int i = 0; i < 4; i++) {
        int c = threadIdx.x + i * 256;
        out[(size_t)row * DMODEL + c] = rtf(v[i] * r * w[c]);
    }
}

// ---------------- TF32 tensor-core GEMM, 3-stage cp.async pipeline ----------------
// C[M,N] = A[M,K]@B[K,N]; mode 0: plain, 1: +Res, 2: C = rtf(silu(Res)*acc)
// BM=128 BN=128 BK=16, 256 threads, warp grid 2(M)x4(N), warp tile 64x32.
#define AS_STRIDE 20
#define AS_ELEMS  (128 * AS_STRIDE)  // 2560
#define BS_STRIDE 136
#define BS_ELEMS  (16 * BS_STRIDE)   // 2176
#define TG_SMEM   (3 * (AS_ELEMS + BS_ELEMS) * 4)  // 56832 bytes
__global__ __launch_bounds__(256, 2) void tgemm_kernel(const float* __restrict__ A,
                                                       const float* __restrict__ B,
                                                       const float* __restrict__ Res,
                                                       float* __restrict__ C,
                                                       int M, int N, int K, int mode) {
    extern __shared__ float sm[];
    float* Asm = sm;                       // 3 x [128][20]
    float* Bsm = sm + 3 * AS_ELEMS;        // 3 x [16][136]
    int bm = blockIdx.y * 128, bn = blockIdx.x * 128;
    int t = threadIdx.x;
    int warp = t >> 5, lane = t & 31;
    int wm = warp & 1, wn = warp >> 1;
    int g = lane >> 2, tg = lane & 3;

    int ar0 = t >> 2, ac0 = (t & 3) * 4;
    int br0 = t >> 5, bc0 = (t & 31) * 4;
    bool bok = (bn + bc0) < N;

    float acc[4][4][4];
#pragma unroll
    for (int mi = 0; mi < 4; mi++)
#pragma unroll
        for (int ni = 0; ni < 4; ni++)
#pragma unroll
            for (int j = 0; j < 4; j++) acc[mi][ni][j] = 0.f;

    auto issue = [&](int buf, int k0) {
        float* as = Asm + buf * AS_ELEMS;
        float* bs = Bsm + buf * BS_ELEMS;
        cp16(&as[ar0 * AS_STRIDE + ac0], A + (size_t)(bm + ar0) * K + k0 + ac0);
        cp16(&as[(ar0 + 64) * AS_STRIDE + ac0], A + (size_t)(bm + ar0 + 64) * K + k0 + ac0);
        if (bok) {
            cp16(&bs[br0 * BS_STRIDE + bc0], B + (size_t)(k0 + br0) * N + bn + bc0);
            cp16(&bs[(br0 + 8) * BS_STRIDE + bc0], B + (size_t)(k0 + br0 + 8) * N + bn + bc0);
        } else {
            float4 z = make_float4(0.f, 0.f, 0.f, 0.f);
            *(float4*)&bs[br0 * BS_STRIDE + bc0] = z;
            *(float4*)&bs[(br0 + 8) * BS_STRIDE + bc0] = z;
        }
        asm volatile("cp.async.commit_group;");
    };

    int nk = K / 16;
    issue(0, 0);
    issue(1, 16);
    int buf = 0;
    for (int it = 0; it < nk; it++) {
        if (it + 2 < nk) {
            issue((it + 2) % 3, (it + 2) * 16);
            asm volatile("cp.async.wait_group 2;");
        } else if (it + 1 < nk) {
            asm volatile("cp.async.wait_group 1;");
        } else {
            asm volatile("cp.async.wait_group 0;");
        }
        __syncthreads();
        const float* as = Asm + buf * AS_ELEMS;
        const float* bs = Bsm + buf * BS_ELEMS;
#pragma unroll
        for (int kk = 0; kk < 16; kk += 8) {
            uint32_t af[4][4], bf[4][2];
#pragma unroll
            for (int mi = 0; mi < 4; mi++) {
                int r = wm * 64 + mi * 16 + g;
                af[mi][0] = __float_as_uint(as[r * AS_STRIDE + kk + tg]);
                af[mi][1] = __float_as_uint(as[(r + 8) * AS_STRIDE + kk + tg]);
                af[mi][2] = __float_as_uint(as[r * AS_STRIDE + kk + tg + 4]);
                af[mi][3] = __float_as_uint(as[(r + 8) * AS_STRIDE + kk + tg + 4]);
            }
#pragma unroll
            for (int ni = 0; ni < 4; ni++) {
                int n0 = wn * 32 + ni * 8 + g;
                bf[ni][0] = __float_as_uint(bs[(kk + tg) * BS_STRIDE + n0]);
                bf[ni][1] = __float_as_uint(bs[(kk + tg + 4) * BS_STRIDE + n0]);
            }
#pragma unroll
            for (int mi = 0; mi < 4; mi++)
#pragma unroll
                for (int ni = 0; ni < 4; ni++) mma_tf32(acc[mi][ni], af[mi], bf[ni]);
        }
        __syncthreads();
        buf = (buf + 1) % 3;
    }

#pragma unroll
    for (int mi = 0; mi < 4; mi++) {
        int r0 = bm + wm * 64 + mi * 16 + g;
#pragma unroll
        for (int ni = 0; ni < 4; ni++) {
            int c0 = bn + wn * 32 + ni * 8 + 2 * tg;
            if (c0 < N) {
                float v[4] = {acc[mi][ni][0], acc[mi][ni][1], acc[mi][ni][2], acc[mi][ni][3]};
                size_t o0 = (size_t)r0 * N + c0;
                size_t o1 = (size_t)(r0 + 8) * N + c0;
                if (mode == 1) {
                    v[0] += Res[o0]; v[1] += Res[o0 + 1];
                    v[2] += Res[o1]; v[3] += Res[o1 + 1];
                } else if (mode == 2) {
                    float r00 = Res[o0], r01 = Res[o0 + 1], r10 = Res[o1], r11 = Res[o1 + 1];
                    v[0] = rtf(r00 / (1.f + expf(-r00)) * v[0]);
                    v[1] = rtf(r01 / (1.f + expf(-r01)) * v[1]);
                    v[2] = rtf(r10 / (1.f + expf(-r10)) * v[2]);
                    v[3] = rtf(r11 / (1.f + expf(-r11)) * v[3]);
                }
                *(float2*)&C[o0] = make_float2(v[0], v[1]);
                *(float2*)&C[o1] = make_float2(v[2], v[3]);
            }
        }
    }
}

// ---------------- per-token preprocessing ----------------
__global__ __launch_bounds__(256) void preproc_kernel(
    const float* __restrict__ proj, const float* __restrict__ A_log,
    const float* __restrict__ D_param, const float* __restrict__ dt_bias,
    const float* __restrict__ B_bias, const float* __restrict__ C_bias,
    const float* __restrict__ Bn_w, const float* __restrict__ Cn_w,
    float* __restrict__ xg, float* __restrict__ Bn, float* __restrict__ Cn,
    float* __restrict__ dtb, float* __restrict__ Ab, float* __restrict__ skipb) {
    int tok = blockIdx.x;
    const float* p = proj + (size_t)tok * PROJ;
    int warp = threadIdx.x >> 5, lane = threadIdx.x & 31;
    for (int h = warp; h < NHEADS; h += 8) {
        float xb = p[DT_OFF + h] + dt_bias[h];
        float dt = xb > 20.f ? xb : log1pf(expf(xb));
        float Av = -expf(A_log[h]) * dt;
        float alpha = expf(Av);
        float gamma = (alpha - 1.f) / (Av + 1e-6f) * 0.5f + 1.f;
        if (lane == 0) {
            dtb[tok * NHEADS + h] = dt;
            Ab[tok * NHEADS + h] = Av;
        }
        float xs0 = p[XS_OFF + h * 64 + lane];
        float xs1 = p[XS_OFF + h * 64 + 32 + lane];
        float ssum = xs0 + xs1;
#pragma unroll
        for (int o = 16; o; o >>= 1) ssum += __shfl_xor_sync(0xffffffffu, ssum, o);
        if (lane == 0) skipb[tok * NHEADS + h] = D_param[h] * ssum;
        xg[(size_t)tok * DINNER + h * 64 + lane] = xs0 * gamma;
        xg[(size_t)tok * DINNER + h * 64 + 32 + lane] = xs1 * gamma;
        float b0 = p[B_OFF + h * 64 + lane], b1 = p[B_OFF + h * 64 + 32 + lane];
        float bs = b0 * b0 + b1 * b1;
#pragma unroll
        for (int o = 16; o; o >>= 1) bs += __shfl_xor_sync(0xffffffffu, bs, o);
        float br = rsqrtf(bs / 64.f + 1e-5f);
        Bn[(size_t)tok * DINNER + h * 64 + lane] = b0 * br * Bn_w[lane] + B_bias[h * 64 + lane];
        Bn[(size_t)tok * DINNER + h * 64 + 32 + lane] =
            b1 * br * Bn_w[32 + lane] + B_bias[h * 64 + 32 + lane];
        float c0 = p[C_OFF + h * 64 + lane], c1 = p[C_OFF + h * 64 + 32 + lane];
        float cs = c0 * c0 + c1 * c1;
#pragma unroll
        for (int o = 16; o; o >>= 1) cs += __shfl_xor_sync(0xffffffffu, cs, o);
        float cr = rsqrtf(cs / 64.f + 1e-5f);
        Cn[(size_t)tok * DINNER + h * 64 + lane] = c0 * cr * Cn_w[lane] + C_bias[h * 64 + lane];
        Cn[(size_t)tok * DINNER + h * 64 + 32 + lane] =
            c1 * cr * Cn_w[32 + lane] + C_bias[h * 64 + 32 + lane];
    }
}

// ---------------- theta cumsum pass 1 (per 512-token segment) ----------------
__global__ __launch_bounds__(1024) void theta_scan1(const float* __restrict__ proj,
                                                    const float* __restrict__ dtb,
                                                    float* __restrict__ cum,
                                                    float* __restrict__ segsum) {
    int blk = blockIdx.x;
    int seg = blk & 7, h = (blk >> 3) & 31, b = blk >> 8;
    int w = threadIdx.x >> 5, lane = threadIdx.x & 31;
    __shared__ float T[32][33];
    __shared__ float O[32][33];
    __shared__ float Dt[32];
    int s0 = b * SEQLEN + seg * 512;
    float carry = 0.f;
    for (int it = 0; it < 16; it++) {
        int tk = s0 + it * 32;
        T[w][lane] = proj[(size_t)(tk + w) * PROJ + TH_OFF + h * 32 + lane];
        if (w == 0) Dt[lane] = dtb[(tk + lane) * NHEADS + h];
        __syncthreads();
        float v = Dt[lane] * T[lane][w];
#pragma unroll
        for (int o = 1; o < 32; o <<= 1) {
            float tv = __shfl_up_sync(0xffffffffu, v, o);
            if (lane >= o) v += tv;
        }
        v += carry;
        float cnew = __shfl_sync(0xffffffffu, v, 31);
        O[lane][w] = v;
        __syncthreads();
        cum[(size_t)(tk + w) * 1024 + h * 32 + lane] = O[w][lane];
        carry = cnew;
    }
    if (lane == 0) segsum[blk * 32 + w] = carry;
}

// ---------------- pass 2 fused with RoPE: ang = cum + seg offset, rotate B/C ----------
__global__ __launch_bounds__(1024) void theta_rope_kernel(const float* __restrict__ cum,
                                                          const float* __restrict__ segsum,
                                                          float* __restrict__ Bn,
                                                          float* __restrict__ Cn) {
    int blk = blockIdx.x;
    int seg = blk & 7, h = (blk >> 3) & 31, b = blk >> 8;
    int w = threadIdx.x >> 5, lane = threadIdx.x & 31;
    int bh8 = (b * 32 + h) * 8;
    float off = 0.f;
    for (int s = 0; s < seg; s++) off += segsum[(bh8 + s) * 32 + lane];
    int s0 = b * SEQLEN + seg * 512;
    for (int it = 0; it < 16; it++) {
        int tok = s0 + it * 32 + w;
        float ang = cum[(size_t)tok * 1024 + h * 32 + lane] + off;
        float sn, cs;
        __sincosf(ang, &sn, &cs);
        size_t base = (size_t)tok * DINNER + h * 64 + 2 * lane;
        float2 bv = *(float2*)&Bn[base];
        *(float2*)&Bn[base] = make_float2(cs * bv.x - sn * bv.y, sn * bv.x + cs * bv.y);
        float2 cv = *(float2*)&Cn[base];
        *(float2*)&Cn[base] = make_float2(cs * cv.x - sn * cv.y, sn * cv.x + cs * cv.y);
    }
}

// ---------------- per-chunk: states[n,p], Bx[n,p], decay scalars ----------------
__global__ __launch_bounds__(256) void ssd_chunk_kernel(
    const float* __restrict__ xg, const float* __restrict__ Bn,
    const float* __restrict__ Ab, float* __restrict__ states, float* __restrict__ Bx,
    float* __restrict__ rowsum, float* __restrict__ expac, float* __restrict__ dc) {
    int idx = blockIdx.x;
    int c = idx & 63, h = (idx >> 6) & 31, b = idx >> 11;
    int tokbase = b * SEQLEN + c * 64;
    __shared__ float Xs[64][64];
    __shared__ float Bs[64][64];
    __shared__ float Ac[64];
    __shared__ float decs[64];
    int t = threadIdx.x;
    if (t < 64) Ac[t] = Ab[(tokbase + t) * NHEADS + h];
    __syncthreads();
    if (t == 0) {
        float s = 0.f;
        for (int l = 0; l < 64; l++) {
            s += Ac[l];
            Ac[l] = s;
        }
    }
    __syncthreads();
    float alast = Ac[63];
    if (t < 64) {
        decs[t] = expf(alast - Ac[t]);
        expac[(size_t)idx * 64 + t] = expf(Ac[t]);
        float rs = 64.f - (float)t;
        for (int s2 = 0; s2 < t; s2++) rs += expf(Ac[t] - Ac[s2]);
        rowsum[(size_t)idx * 64 + t] = rs;
    }
    if (t == 0) dc[idx] = expf(alast);
    {
        int row = t >> 2, j0 = t & 3;
        const float* xr = xg + (size_t)(tokbase + row) * DINNER + h * 64;
        const float* br = Bn + (size_t)(tokbase + row) * DINNER + h * 64;
#pragma unroll
        for (int j = j0; j < 16; j += 4) {
            *(float4*)&Xs[row][j * 4] = *(const float4*)&xr[j * 4];
            *(float4*)&Bs[row][j * 4] = *(const float4*)&br[j * 4];
        }
    }
    __syncthreads();
    int nt = (t >> 4) * 4, pt = (t & 15) * 4;
    float a1[4][4], a2[4][4];
#pragma unroll
    for (int i = 0; i < 4; i++)
#pragma unroll
        for (int j = 0; j < 4; j++) { a1[i][j] = 0.f; a2[i][j] = 0.f; }
    for (int l = 0; l < 64; l++) {
        float dv = decs[l];
        float bv[4], xv[4];
        *(float4*)bv = *(const float4*)&Bs[l][nt];
        *(float4*)xv = *(const float4*)&Xs[l][pt];
#pragma unroll
        for (int i = 0; i < 4; i++) {
            float bd = bv[i] * dv;
#pragma unroll
            for (int j = 0; j < 4; j++) {
                a1[i][j] += bv[i] * xv[j];
                a2[i][j] += bd * xv[j];
            }
        }
    }
    size_t ob = (size_t)idx * 4096;
#pragma unroll
    for (int i = 0; i < 4; i++) {
        int n = nt + i;
        *(float4*)&Bx[ob + n * 64 + pt] = make_float4(a1[i][0], a1[i][1], a1[i][2], a1[i][3]);
        *(float4*)&states[ob + n * 64 + pt] = make_float4(a2[i][0], a2[i][1], a2[i][2], a2[i][3]);
    }
}

// ---------------- inter-chunk scan (float4, 512 blocks) ----------------
__global__ __launch_bounds__(256) void ssd_scan_kernel(float* __restrict__ states,
                                                       const float* __restrict__ dc) {
    int bh = blockIdx.x >> 2, slice = blockIdx.x & 3;
    size_t off = (size_t)slice * 1024 + threadIdx.x * 4;
    float4 carry = make_float4(0.f, 0.f, 0.f, 0.f);
    for (int c = 0; c < NCHUNK; c++) {
        size_t base = ((size_t)bh * 64 + c) * 4096 + off;
        float dec = __ldg(&dc[bh * 64 + c]);
        float4 s = *(float4*)&states[base];
        carry.x = carry.x * dec + s.x;
        carry.y = carry.y * dec + s.y;
        carry.z = carry.z * dec + s.z;
        carry.w = carry.w * dec + s.w;
        *(float4*)&states[base] = carry;
    }
}

// ---------------- Y + skip, gated by silu(z) -> yg (tf32-rounded) ----------------
__global__ __launch_bounds__(256) void ssd_y_kernel(
    const float* __restrict__ Cn, const float* __restrict__ Bx,
    const float* __restrict__ states, const float* __restrict__ rowsum,
    const float* __restrict__ expac, const float* __restrict__ skipb,
    const float* __restrict__ proj, float* __restrict__ yg) {
    int idx = blockIdx.x;
    int c = idx & 63, h = (idx >> 6) & 31, b = idx >> 11;
    int tokbase = b * SEQLEN + c * 64;
    __shared__ float Ct[64][64];
    __shared__ float Bxs[64][64];
    __shared__ float Ss[64][64];
    int t = threadIdx.x;
    size_t sb = (size_t)idx * 4096;
#pragma unroll
    for (int i = 0; i < 4; i++) {
        int e = i * 1024 + t * 4;
        *(float4*)(&Bxs[0][0] + e) = *(const float4*)&Bx[sb + e];
        *(float4*)(&Ss[0][0] + e) = *(const float4*)&states[sb + e];
    }
    {
        int row = t >> 2, j0 = t & 3;
        const float* cr = Cn + (size_t)(tokbase + row) * DINNER + h * 64;
#pragma unroll
        for (int j = j0; j < 16; j += 4) {
            float4 v = *(const float4*)&cr[j * 4];
            Ct[j * 4 + 0][row] = v.x;
            Ct[j * 4 + 1][row] = v.y;
            Ct[j * 4 + 2][row] = v.z;
            Ct[j * 4 + 3][row] = v.w;
        }
    }
    __syncthreads();
    int lt = (t >> 4) * 4, pt = (t & 15) * 4;
    float p1[4][4], p2[4][4];
#pragma unroll
    for (int i = 0; i < 4; i++)
#pragma unroll
        for (int j = 0; j < 4; j++) { p1[i][j] = 0.f; p2[i][j] = 0.f; }
    for (int n = 0; n < 64; n++) {
        float cv[4], bv[4], sv[4];
        *(float4*)cv = *(const float4*)&Ct[n][lt];
        *(float4*)bv = *(const float4*)&Bxs[n][pt];
        *(float4*)sv = *(const float4*)&Ss[n][pt];
#pragma unroll
        for (int i = 0; i < 4; i++)
#pragma unroll
            for (int j = 0; j < 4; j++) {
                p1[i][j] += cv[i] * bv[j];
                p2[i][j] += cv[i] * sv[j];
            }
    }
#pragma unroll
    for (int i = 0; i < 4; i++) {
        int l = lt + i;
        int tok = tokbase + l;
        float rs = rowsum[(size_t)idx * 64 + l];
        float ea = expac[(size_t)idx * 64 + l];
        float sk = skipb[tok * NHEADS + h];
        float4 z4 = *(const float4*)(proj + (size_t)tok * PROJ + h * 64 + pt);
        float zz[4] = {z4.x, z4.y, z4.z, z4.w};
        float o[4];
#pragma unroll
        for (int j = 0; j < 4; j++) {
            float y = rs * p1[i][j] + ea * p2[i][j] + sk;
            float z = zz[j];
            o[j] = rtf(y * (z / (1.f + expf(-z))));
        }
        *(float4*)&yg[(size_t)tok * DINNER + h * 64 + pt] = make_float4(o[0], o[1], o[2], o[3]);
    }
}

// ---------------- launch ----------------
extern "C" void kernel_launch(void* const* d_in, const int* in_sizes, int n_in,
                              void* d_out, int out_size) {
    (void)in_sizes; (void)n_in; (void)out_size;
    const float* x = (const float*)d_in[0];
    const float* n1w = (const float*)d_in[1];
    const float* n2w = (const float*)d_in[2];
    const float* W_in = (const float*)d_in[3];
    const float* W_out = (const float*)d_in[4];
    const float* A_log = (const float*)d_in[5];
    const float* Dp = (const float*)d_in[6];
    const float* dtbias = (const float*)d_in[7];
    const float* Bbias = (const float*)d_in[8];
    const float* Cbias = (const float*)d_in[9];
    const float* Bnw = (const float*)d_in[10];
    const float* Cnw = (const float*)d_in[11];
    const float* Wg = (const float*)d_in[12];
    const float* Wu = (const float*)d_in[13];
    const float* Wd = (const float*)d_in[14];
    float* out = (float*)d_out;

    float *h, *proj, *xg, *Bn, *Cn, *dtb, *Ab, *skipb, *cum, *segsum, *states, *Bx;
    float *rowsum, *expac, *dc, *x2, *gb, *ub;
    float *winr, *woutr, *wgr, *wur, *wdr;
    cudaGetSymbolAddress((void**)&h, g_h);
    cudaGetSymbolAddress((void**)&proj, g_proj);
    cudaGetSymbolAddress((void**)&xg, g_xg);
    cudaGetSymbolAddress((void**)&Bn, g_Bn);
    cudaGetSymbolAddress((void**)&Cn, g_Cn);
    cudaGetSymbolAddress((void**)&dtb, g_dt);
    cudaGetSymbolAddress((void**)&Ab, g_A);
    cudaGetSymbolAddress((void**)&skipb, g_skip);
    cudaGetSymbolAddress((void**)&cum, g_cum);
    cudaGetSymbolAddress((void**)&segsum, g_segsum);
    cudaGetSymbolAddress((void**)&states, g_states);
    cudaGetSymbolAddress((void**)&Bx, g_Bx);
    cudaGetSymbolAddress((void**)&rowsum, g_rowsum);
    cudaGetSymbolAddress((void**)&expac, g_expac);
    cudaGetSymbolAddress((void**)&dc, g_dc);
    cudaGetSymbolAddress((void**)&x2, g_x2);
    cudaGetSymbolAddress((void**)&gb, g_gb);
    cudaGetSymbolAddress((void**)&ub, g_ub);
    (void)ub;
    cudaGetSymbolAddress((void**)&winr, g_Winr);
    cudaGetSymbolAddress((void**)&woutr, g_Woutr);
    cudaGetSymbolAddress((void**)&wgr, g_Wgr);
    cudaGetSymbolAddress((void**)&wur, g_Wur);
    cudaGetSymbolAddress((void**)&wdr, g_Wdr);

    static int attr_done = 0;
    if (!attr_done) {
        cudaFuncSetAttribute(tgemm_kernel, cudaFuncAttributeMaxDynamicSharedMemorySize,
                             TG_SMEM);
        attr_done = 1;
    }

    // 0) round weights to nearest-tf32 (single launch)
    round_all_kernel<<<(RTOT + 255) / 256, 256>>>(winr, W_in, woutr, W_out, wgr, Wg, wur, Wu,
                                                  wdr, Wd);
    // 1) h = rmsnorm(x)
    rmsnorm_kernel<<<TOKENS, 256>>>(x, n1w, h);
    // 2) proj = h @ W_in
    tgemm_kernel<<<dim3((PROJ + 127) / 128, TOKENS / 128), 256, TG_SMEM>>>(
        h, winr, nullptr, proj, TOKENS, PROJ, DMODEL, 0);
    // 3) per-token preprocessing
    preproc_kernel<<<TOKENS, 256>>>(proj, A_log, Dp, dtbias, Bbias, Cbias, Bnw, Cnw, xg, Bn,
                                    Cn, dtb, Ab, skipb);
    // 4) cumtheta scan + fused RoPE
    theta_scan1<<<2 * NHEADS * 8, 1024>>>(proj, dtb, cum, segsum);
    theta_rope_kernel<<<2 * NHEADS * 8, 1024>>>(cum, segsum, Bn, Cn);
    // 5) per-chunk states/Bx + decay scalars
    ssd_chunk_kernel<<<2 * NHEADS * NCHUNK, 256>>>(xg, Bn, Ab, states, Bx, rowsum, expac, dc);
    // 6) inter-chunk scan
    ssd_scan_kernel<<<2 * NHEADS * 4, 256>>>(states, dc);
    // 7) Y + skip + silu(z) gate -> yg (reuses xg)
    ssd_y_kernel<<<2 * NHEADS * NCHUNK, 256>>>(Cn, Bx, states, rowsum, expac, skipb, proj, xg);
    // 8) x2 = x + yg @ W_out
    tgemm_kernel<<<dim3(DMODEL / 128, TOKENS / 128), 256, TG_SMEM>>>(
        xg, woutr, x, x2, TOKENS, DMODEL, DINNER, 1);
    // 9) h2 = rmsnorm(x2)
    rmsnorm_kernel<<<TOKENS, 256>>>(x2, n2w, h);
    // 10) gb = h2 @ Wg
    tgemm_kernel<<<dim3(DMLP / 128, TOKENS / 128), 256, TG_SMEM>>>(
        h, wgr, nullptr, gb, TOKENS, DMLP, DMODEL, 0);
    // 11) gb = rtf(silu(gb) * (h2 @ Wu))   (gate fused into epilogue)
    tgemm_kernel<<<dim3(DMLP / 128, TOKENS / 128), 256, TG_SMEM>>>(
        h, wur, gb, gb, TOKENS, DMLP, DMODEL, 2);
    // 12) out = x2 + gb @ Wd
    tgemm_kernel<<<dim3(DMODEL / 128, TOKENS / 128), 256, TG_SMEM>>>(
        gb, wdr, x2, out, TOKENS, DMODEL, DMLP, 1);
}

// round 10
// speedup vs baseline: 4.7254x; 1.5265x over previous
#include <cuda_runtime.h>
#include <cuda_fp16.h>
#include <mma.h>
#include <math.h>
#include <stdint.h>

using namespace nvcuda;

#define TOKENS   8192
#define SEQLEN   4096
#define DMODEL   1024
#define DINNER   2048
#define NHEADS   32
#define HEADDIM  64
#define DSTATE   64
#define CHUNKL   64
#define NCHUNK   64
#define DMLP     2560
#define PROJ     9248
#define NPAD_IN  9472
#define XS_OFF   2048
#define B_OFF    4096
#define C_OFF    6144
#define DT_OFF   8192
#define TH_OFF   8224
#define YSCALE   0.015625f   /* 1/64: keep ygh inside fp16 range (exact pow2) */
#define YUNSCALE 64.0f

// ---------------- scratch (device globals: no allocation allowed) ----------------
__device__ float g_proj[75759616];
__device__ float g_xg[TOKENS * DINNER];
__device__ float g_Bn[TOKENS * DINNER];
__device__ float g_Cn[TOKENS * DINNER];
__device__ float g_dt[TOKENS * NHEADS];
__device__ float g_A[TOKENS * NHEADS];
__device__ float g_skip[TOKENS * NHEADS];
__device__ float g_cum[TOKENS * NHEADS * (DSTATE / 2)];
__device__ float g_segsum[2 * NHEADS * 8 * 32];
__device__ float g_states[2 * NHEADS * NCHUNK * HEADDIM * DSTATE];
__device__ float g_Bx[2 * NHEADS * NCHUNK * HEADDIM * DSTATE];
__device__ float g_rowsum[2 * NHEADS * NCHUNK * CHUNKL];
__device__ float g_expac[2 * NHEADS * NCHUNK * CHUNKL];
__device__ float g_dc[2 * NHEADS * NCHUNK];
__device__ float g_x2[TOKENS * DMODEL];
__device__ float g_gb[TOKENS * DMLP];
// half activations (GEMM A operands) -- 16B aligned for cp.async
__device__ __align__(16) __half g_hh[TOKENS * DMODEL];
__device__ __align__(16) __half g_ygh[TOKENS * DINNER];
__device__ __align__(16) __half g_gbh[TOKENS * DMLP];
// transposed + fp16 weights: Wt[n][k] -- 16B aligned for cp.async
__device__ __align__(16) __half g_Wtin[NPAD_IN * DMODEL];
__device__ __align__(16) __half g_Wtout[DMODEL * DINNER];
__device__ __align__(16) __half g_Wtg[DMLP * DMODEL];
__device__ __align__(16) __half g_Wtu[DMLP * DMODEL];
__device__ __align__(16) __half g_Wtd[DMODEL * DMLP];

// ---------------- helpers ----------------
__device__ __forceinline__ void cp16(void* smem, const void* g) {
    uint32_t s = (uint32_t)__cvta_generic_to_shared(smem);
    asm volatile("cp.async.cg.shared.global [%0], [%1], 16;" ::"r"(s), "l"(g));
}

// ---------------- weight transpose + fp16 convert: in[K][N] -> out[Npad][K] ----------------
__global__ __launch_bounds__(256) void wtransh_kernel(const float* __restrict__ in,
                                                      __half* __restrict__ out, int K, int N) {
    __shared__ float tile[32][33];
    int n0 = blockIdx.x * 32, k0 = blockIdx.y * 32;
    int tx = threadIdx.x & 31, ty = threadIdx.x >> 5;
#pragma unroll
    for (int i = ty; i < 32; i += 8) {
        int n = n0 + tx;
        tile[i][tx] = (n < N) ? in[(size_t)(k0 + i) * N + n] : 0.f;
    }
    __syncthreads();
#pragma unroll
    for (int i = ty; i < 32; i += 8)
        out[(size_t)(n0 + i) * K + k0 + tx] = __float2half_rn(tile[tx][i]);
}

// ---------------- FP16 wmma GEMM: C[M,N] = ascale*(A[M,K] @ Bt[n][k]^T) (+epilogue) -----
// BM=BN=128, BK=32, 256 threads, warp grid 2(M)x4(N), warp tile 64x32 (4x2 wmma 16x16x16).
// mode 0: C=v; 1: C=v+Res; 2: Ch = half(silu(Res)*v)     where v = ascale*acc
#define AST 40       // halves per smem row (32 + 8 pad); 80B stride (mult of 16B)
#define HBUF (128 * AST)
__global__ __launch_bounds__(256, 2) void hgemm_kernel(const __half* __restrict__ A,
                                                       const __half* __restrict__ Bt,
                                                       const float* __restrict__ Res,
                                                       float* __restrict__ C,
                                                       __half* __restrict__ Ch,
                                                       int M, int N, int K, int mode,
                                                       float ascale) {
    // union: load buffers (2x(A+B) = 40960 B)  /  epilogue staging (64x136 f32 = 34816 B)
    __shared__ alignas(32) __half smem_h[4 * HBUF];
    __half* As0 = smem_h;              // [2][HBUF]
    __half* Bs0 = smem_h + 2 * HBUF;   // [2][HBUF]
    float* stage = (float*)smem_h;     // [64][136] overlay

    int bm = blockIdx.y * 128, bn = blockIdx.x * 128;
    int t = threadIdx.x;
    int warp = t >> 5;
    int wm = warp & 1, wn = warp >> 1;

    // tile coverage: 128 rows x 32 halves = 512 x 16B chunks per array; 256 thr x 2 = 512.
    int lrow = t >> 2, lcol = (t & 3) * 8;

    wmma::fragment<wmma::accumulator, 16, 16, 16, float> acc[4][2];
#pragma unroll
    for (int mi = 0; mi < 4; mi++)
#pragma unroll
        for (int nn = 0; nn < 2; nn++) wmma::fill_fragment(acc[mi][nn], 0.f);

    auto issue = [&](int buf, int k0) {
        __half* as = As0 + buf * HBUF;
        __half* bs = Bs0 + buf * HBUF;
        cp16(&as[lrow * AST + lcol], A + (size_t)(bm + lrow) * K + k0 + lcol);
        cp16(&as[(lrow + 64) * AST + lcol], A + (size_t)(bm + lrow + 64) * K + k0 + lcol);
        cp16(&bs[lrow * AST + lcol], Bt + (size_t)(bn + lrow) * K + k0 + lcol);
        cp16(&bs[(lrow + 64) * AST + lcol], Bt + (size_t)(bn + lrow + 64) * K + k0 + lcol);
        asm volatile("cp.async.commit_group;");
    };

    int nk = K / 32;
    issue(0, 0);
    for (int it = 0; it < nk; it++) {
        int buf = it & 1;
        if (it + 1 < nk) {
            issue(buf ^ 1, (it + 1) * 32);
            asm volatile("cp.async.wait_group 1;");
        } else {
            asm volatile("cp.async.wait_group 0;");
        }
        __syncthreads();
        const __half* as = As0 + buf * HBUF;
        const __half* bs = Bs0 + buf * HBUF;
#pragma unroll
        for (int kk = 0; kk < 32; kk += 16) {
            wmma::fragment<wmma::matrix_a, 16, 16, 16, __half, wmma::row_major> af[4];
            wmma::fragment<wmma::matrix_b, 16, 16, 16, __half, wmma::col_major> bf[2];
#pragma unroll
            for (int mi = 0; mi < 4; mi++)
                wmma::load_matrix_sync(af[mi], &as[(wm * 64 + mi * 16) * AST + kk], AST);
#pragma unroll
            for (int nn = 0; nn < 2; nn++)
                wmma::load_matrix_sync(bf[nn], &bs[(wn * 32 + nn * 16) * AST + kk], AST);
#pragma unroll
            for (int mi = 0; mi < 4; mi++)
#pragma unroll
                for (int nn = 0; nn < 2; nn++)
                    wmma::mma_sync(acc[mi][nn], af[mi], bf[nn], acc[mi][nn]);
        }
        __syncthreads();
    }

    // epilogue: two 64-row passes through smem staging (overlays load buffers)
    for (int p = 0; p < 2; p++) {
        __syncthreads();
        if (wm == p) {
#pragma unroll
            for (int mi = 0; mi < 4; mi++)
#pragma unroll
                for (int nn = 0; nn < 2; nn++)
                    wmma::store_matrix_sync(&stage[(mi * 16) * 136 + wn * 32 + nn * 16],
                                            acc[mi][nn], 136, wmma::mem_row_major);
        }
        __syncthreads();
#pragma unroll 4
        for (int u = t; u < 64 * 64; u += 256) {
            int row = u >> 6, c2 = (u & 63) * 2;
            int gc = bn + c2;
            if (gc < N) {
                int gr = bm + p * 64 + row;
                float v0 = stage[row * 136 + c2] * ascale;
                float v1 = stage[row * 136 + c2 + 1] * ascale;
                size_t go = (size_t)gr * N + gc;
                if (mode == 2) {
                    float r0 = Res[go], r1 = Res[go + 1];
                    v0 = r0 / (1.f + expf(-r0)) * v0;
                    v1 = r1 / (1.f + expf(-r1)) * v1;
                    *(__half2*)&Ch[go] = __floats2half2_rn(v0, v1);
                } else {
                    if (mode == 1) {
                        v0 += Res[go];
                        v1 += Res[go + 1];
                    }
                    *(float2*)&C[go] = make_float2(v0, v1);
                }
            }
        }
    }
}

// ---------------- rmsnorm over D=1024 (half output) ----------------
__global__ __launch_bounds__(256) void rmsnorm_kernel(const float* __restrict__ x,
                                                      const float* __restrict__ w,
                                                      __half* __restrict__ out) {
    int row = blockIdx.x;
    const float* xr = x + (size_t)row * DMODEL;
    float v[4];
    float s = 0.f;
#pragma unroll
    for (int i = 0; i < 4; i++) {
        v[i] = xr[threadIdx.x + i * 256];
        s += v[i] * v[i];
    }
    __shared__ float red[8];
#pragma unroll
    for (int o = 16; o; o >>= 1) s += __shfl_xor_sync(0xffffffffu, s, o);
    if ((threadIdx.x & 31) == 0) red[threadIdx.x >> 5] = s;
    __syncthreads();
    if (threadIdx.x == 0) {
        float tt = 0.f;
#pragma unroll
        for (int i = 0; i < 8; i++) tt += red[i];
        red[0] = rsqrtf(tt / (float)DMODEL + 1e-5f);
    }
    __syncthreads();
    float r = red[0];
#pragma unroll
    for (int i = 0; i < 4; i++) {
        int c = threadIdx.x + i * 256;
        out[(size_t)row * DMODEL + c] = __float2half_rn(v[i] * r * w[c]);
    }
}

// ---------------- per-token preprocessing ----------------
__global__ __launch_bounds__(256) void preproc_kernel(
    const float* __restrict__ proj, const float* __restrict__ A_log,
    const float* __restrict__ D_param, const float* __restrict__ dt_bias,
    const float* __restrict__ B_bias, const float* __restrict__ C_bias,
    const float* __restrict__ Bn_w, const float* __restrict__ Cn_w,
    float* __restrict__ xg, float* __restrict__ Bn, float* __restrict__ Cn,
    float* __restrict__ dtb, float* __restrict__ Ab, float* __restrict__ skipb) {
    int tok = blockIdx.x;
    const float* p = proj + (size_t)tok * PROJ;
    int warp = threadIdx.x >> 5, lane = threadIdx.x & 31;
    for (int h = warp; h < NHEADS; h += 8) {
        float xb = p[DT_OFF + h] + dt_bias[h];
        float dt = xb > 20.f ? xb : log1pf(expf(xb));
        float Av = -expf(A_log[h]) * dt;
        float alpha = expf(Av);
        float gamma = (alpha - 1.f) / (Av + 1e-6f) * 0.5f + 1.f;
        if (lane == 0) {
            dtb[tok * NHEADS + h] = dt;
            Ab[tok * NHEADS + h] = Av;
        }
        float xs0 = p[XS_OFF + h * 64 + lane];
        float xs1 = p[XS_OFF + h * 64 + 32 + lane];
        float ssum = xs0 + xs1;
#pragma unroll
        for (int o = 16; o; o >>= 1) ssum += __shfl_xor_sync(0xffffffffu, ssum, o);
        if (lane == 0) skipb[tok * NHEADS + h] = D_param[h] * ssum;
        xg[(size_t)tok * DINNER + h * 64 + lane] = xs0 * gamma;
        xg[(size_t)tok * DINNER + h * 64 + 32 + lane] = xs1 * gamma;
        float b0 = p[B_OFF + h * 64 + lane], b1 = p[B_OFF + h * 64 + 32 + lane];
        float bs = b0 * b0 + b1 * b1;
#pragma unroll
        for (int o = 16; o; o >>= 1) bs += __shfl_xor_sync(0xffffffffu, bs, o);
        float br = rsqrtf(bs / 64.f + 1e-5f);
        Bn[(size_t)tok * DINNER + h * 64 + lane] = b0 * br * Bn_w[lane] + B_bias[h * 64 + lane];
        Bn[(size_t)tok * DINNER + h * 64 + 32 + lane] =
            b1 * br * Bn_w[32 + lane] + B_bias[h * 64 + 32 + lane];
        float c0 = p[C_OFF + h * 64 + lane], c1 = p[C_OFF + h * 64 + 32 + lane];
        float cs = c0 * c0 + c1 * c1;
#pragma unroll
        for (int o = 16; o; o >>= 1) cs += __shfl_xor_sync(0xffffffffu, cs, o);
        float cr = rsqrtf(cs / 64.f + 1e-5f);
        Cn[(size_t)tok * DINNER + h * 64 + lane] = c0 * cr * Cn_w[lane] + C_bias[h * 64 + lane];
        Cn[(size_t)tok * DINNER + h * 64 + 32 + lane] =
            c1 * cr * Cn_w[32 + lane] + C_bias[h * 64 + 32 + lane];
    }
}

// ---------------- theta cumsum pass 1 ----------------
__global__ __launch_bounds__(1024) void theta_scan1(const float* __restrict__ proj,
                                                    const float* __restrict__ dtb,
                                                    float* __restrict__ cum,
                                                    float* __restrict__ segsum) {
    int blk = blockIdx.x;
    int seg = blk & 7, h = (blk >> 3) & 31, b = blk >> 8;
    int w = threadIdx.x >> 5, lane = threadIdx.x & 31;
    __shared__ float T[32][33];
    __shared__ float O[32][33];
    __shared__ float Dt[32];
    int s0 = b * SEQLEN + seg * 512;
    float carry = 0.f;
    for (int it = 0; it < 16; it++) {
        int tk = s0 + it * 32;
        T[w][lane] = proj[(size_t)(tk + w) * PROJ + TH_OFF + h * 32 + lane];
        if (w == 0) Dt[lane] = dtb[(tk + lane) * NHEADS + h];
        __syncthreads();
        float v = Dt[lane] * T[lane][w];
#pragma unroll
        for (int o = 1; o < 32; o <<= 1) {
            float tv = __shfl_up_sync(0xffffffffu, v, o);
            if (lane >= o) v += tv;
        }
        v += carry;
        float cnew = __shfl_sync(0xffffffffu, v, 31);
        O[lane][w] = v;
        __syncthreads();
        cum[(size_t)(tk + w) * 1024 + h * 32 + lane] = O[w][lane];
        carry = cnew;
    }
    if (lane == 0) segsum[blk * 32 + w] = carry;
}

// ---------------- pass 2 fused with RoPE ----------------
__global__ __launch_bounds__(1024) void theta_rope_kernel(const float* __restrict__ cum,
                                                          const float* __restrict__ segsum,
                                                          float* __restrict__ Bn,
                                                          float* __restrict__ Cn) {
    int blk = blockIdx.x;
    int seg = blk & 7, h = (blk >> 3) & 31, b = blk >> 8;
    int w = threadIdx.x >> 5, lane = threadIdx.x & 31;
    int bh8 = (b * 32 + h) * 8;
    float off = 0.f;
    for (int s = 0; s < seg; s++) off += segsum[(bh8 + s) * 32 + lane];
    int s0 = b * SEQLEN + seg * 512;
    for (int it = 0; it < 16; it++) {
        int tok = s0 + it * 32 + w;
        float ang = cum[(size_t)tok * 1024 + h * 32 + lane] + off;
        float sn, cs;
        __sincosf(ang, &sn, &cs);
        size_t base = (size_t)tok * DINNER + h * 64 + 2 * lane;
        float2 bv = *(float2*)&Bn[base];
        *(float2*)&Bn[base] = make_float2(cs * bv.x - sn * bv.y, sn * bv.x + cs * bv.y);
        float2 cv = *(float2*)&Cn[base];
        *(float2*)&Cn[base] = make_float2(cs * cv.x - sn * cv.y, sn * cv.x + cs * cv.y);
    }
}

// ---------------- per-chunk: states[n,p], Bx[n,p], decay scalars ----------------
__global__ __launch_bounds__(256) void ssd_chunk_kernel(
    const float* __restrict__ xg, const float* __restrict__ Bn,
    const float* __restrict__ Ab, float* __restrict__ states, float* __restrict__ Bx,
    float* __restrict__ rowsum, float* __restrict__ expac, float* __restrict__ dc) {
    int idx = blockIdx.x;
    int c = idx & 63, h = (idx >> 6) & 31, b = idx >> 11;
    int tokbase = b * SEQLEN + c * 64;
    __shared__ float Xs[64][64];
    __shared__ float Bs[64][64];
    __shared__ float Ac[64];
    __shared__ float decs[64];
    int t = threadIdx.x;
    if (t < 64) Ac[t] = Ab[(tokbase + t) * NHEADS + h];
    __syncthreads();
    if (t == 0) {
        float s = 0.f;
        for (int l = 0; l < 64; l++) {
            s += Ac[l];
            Ac[l] = s;
        }
    }
    __syncthreads();
    float alast = Ac[63];
    if (t < 64) {
        decs[t] = expf(alast - Ac[t]);
        expac[(size_t)idx * 64 + t] = expf(Ac[t]);
        float rs = 64.f - (float)t;
        for (int s2 = 0; s2 < t; s2++) rs += expf(Ac[t] - Ac[s2]);
        rowsum[(size_t)idx * 64 + t] = rs;
    }
    if (t == 0) dc[idx] = expf(alast);
    {
        int row = t >> 2, j0 = t & 3;
        const float* xr = xg + (size_t)(tokbase + row) * DINNER + h * 64;
        const float* br = Bn + (size_t)(tokbase + row) * DINNER + h * 64;
#pragma unroll
        for (int j = j0; j < 16; j += 4) {
            *(float4*)&Xs[row][j * 4] = *(const float4*)&xr[j * 4];
            *(float4*)&Bs[row][j * 4] = *(const float4*)&br[j * 4];
        }
    }
    __syncthreads();
    int nt = (t >> 4) * 4, pt = (t & 15) * 4;
    float a1[4][4], a2[4][4];
#pragma unroll
    for (int i = 0; i < 4; i++)
#pragma unroll
        for (int j = 0; j < 4; j++) { a1[i][j] = 0.f; a2[i][j] = 0.f; }
    for (int l = 0; l < 64; l++) {
        float dv = decs[l];
        float bv[4], xv[4];
        *(float4*)bv = *(const float4*)&Bs[l][nt];
        *(float4*)xv = *(const float4*)&Xs[l][pt];
#pragma unroll
        for (int i = 0; i < 4; i++) {
            float bd = bv[i] * dv;
#pragma unroll
            for (int j = 0; j < 4; j++) {
                a1[i][j] += bv[i] * xv[j];
                a2[i][j] += bd * xv[j];
            }
        }
    }
    size_t ob = (size_t)idx * 4096;
#pragma unroll
    for (int i = 0; i < 4; i++) {
        int n = nt + i;
        *(float4*)&Bx[ob + n * 64 + pt] = make_float4(a1[i][0], a1[i][1], a1[i][2], a1[i][3]);
        *(float4*)&states[ob + n * 64 + pt] = make_float4(a2[i][0], a2[i][1], a2[i][2], a2[i][3]);
    }
}

// ---------------- inter-chunk scan ----------------
__global__ __launch_bounds__(256) void ssd_scan_kernel(float* __restrict__ states,
                                                       const float* __restrict__ dc) {
    int bh = blockIdx.x >> 2, slice = blockIdx.x & 3;
    size_t off = (size_t)slice * 1024 + threadIdx.x * 4;
    float4 carry = make_float4(0.f, 0.f, 0.f, 0.f);
    for (int c = 0; c < NCHUNK; c++) {
        size_t base = ((size_t)bh * 64 + c) * 4096 + off;
        float dec = __ldg(&dc[bh * 64 + c]);
        float4 s = *(float4*)&states[base];
        carry.x = carry.x * dec + s.x;
        carry.y = carry.y * dec + s.y;
        carry.z = carry.z * dec + s.z;
        carry.w = carry.w * dec + s.w;
        *(float4*)&states[base] = carry;
    }
}

// ---------------- Y + skip, gated by silu(z) -> yg = half(y_gated/64) ----------------
__global__ __launch_bounds__(256) void ssd_y_kernel(
    const float* __restrict__ Cn, const float* __restrict__ Bx,
    const float* __restrict__ states, const float* __restrict__ rowsum,
    const float* __restrict__ expac, const float* __restrict__ skipb,
    const float* __restrict__ proj, __half* __restrict__ yg) {
    int idx = blockIdx.x;
    int c = idx & 63, h = (idx >> 6) & 31, b = idx >> 11;
    int tokbase = b * SEQLEN + c * 64;
    __shared__ float Ct[64][64];
    __shared__ float Bxs[64][64];
    __shared__ float Ss[64][64];
    int t = threadIdx.x;
    size_t sb = (size_t)idx * 4096;
#pragma unroll
    for (int i = 0; i < 4; i++) {
        int e = i * 1024 + t * 4;
        *(float4*)(&Bxs[0][0] + e) = *(const float4*)&Bx[sb + e];
        *(float4*)(&Ss[0][0] + e) = *(const float4*)&states[sb + e];
    }
    {
        int row = t >> 2, j0 = t & 3;
        const float* cr = Cn + (size_t)(tokbase + row) * DINNER + h * 64;
#pragma unroll
        for (int j = j0; j < 16; j += 4) {
            float4 v = *(const float4*)&cr[j * 4];
            Ct[j * 4 + 0][row] = v.x;
            Ct[j * 4 + 1][row] = v.y;
            Ct[j * 4 + 2][row] = v.z;
            Ct[j * 4 + 3][row] = v.w;
        }
    }
    __syncthreads();
    int lt = (t >> 4) * 4, pt = (t & 15) * 4;
    float p1[4][4], p2[4][4];
#pragma unroll
    for (int i = 0; i < 4; i++)
#pragma unroll
        for (int j = 0; j < 4; j++) { p1[i][j] = 0.f; p2[i][j] = 0.f; }
    for (int n = 0; n < 64; n++) {
        float cv[4], bv[4], sv[4];
        *(float4*)cv = *(const float4*)&Ct[n][lt];
        *(float4*)bv = *(const float4*)&Bxs[n][pt];
        *(float4*)sv = *(const float4*)&Ss[n][pt];
#pragma unroll
        for (int i = 0; i < 4; i++)
#pragma unroll
            for (int j = 0; j < 4; j++) {
                p1[i][j] += cv[i] * bv[j];
                p2[i][j] += cv[i] * sv[j];
            }
    }
#pragma unroll
    for (int i = 0; i < 4; i++) {
        int l = lt + i;
        int tok = tokbase + l;
        float rs = rowsum[(size_t)idx * 64 + l];
        float ea = expac[(size_t)idx * 64 + l];
        float sk = skipb[tok * NHEADS + h];
        float4 z4 = *(const float4*)(proj + (size_t)tok * PROJ + h * 64 + pt);
        float zz[4] = {z4.x, z4.y, z4.z, z4.w};
        float o[4];
#pragma unroll
        for (int j = 0; j < 4; j++) {
            float y = rs * p1[i][j] + ea * p2[i][j] + sk;
            float z = zz[j];
            o[j] = y * (z / (1.f + expf(-z))) * YSCALE;  // exact pow2 downscale
        }
        size_t ob = (size_t)tok * DINNER + h * 64 + pt;
        *(__half2*)&yg[ob] = __floats2half2_rn(o[0], o[1]);
        *(__half2*)&yg[ob + 2] = __floats2half2_rn(o[2], o[3]);
    }
}

// ---------------- launch ----------------
extern "C" void kernel_launch(void* const* d_in, const int* in_sizes, int n_in,
                              void* d_out, int out_size) {
    (void)in_sizes; (void)n_in; (void)out_size;
    const float* x = (const float*)d_in[0];
    const float* n1w = (const float*)d_in[1];
    const float* n2w = (const float*)d_in[2];
    const float* W_in = (const float*)d_in[3];
    const float* W_out = (const float*)d_in[4];
    const float* A_log = (const float*)d_in[5];
    const float* Dp = (const float*)d_in[6];
    const float* dtbias = (const float*)d_in[7];
    const float* Bbias = (const float*)d_in[8];
    const float* Cbias = (const float*)d_in[9];
    const float* Bnw = (const float*)d_in[10];
    const float* Cnw = (const float*)d_in[11];
    const float* Wg = (const float*)d_in[12];
    const float* Wu = (const float*)d_in[13];
    const float* Wd = (const float*)d_in[14];
    float* out = (float*)d_out;

    float *proj, *xg, *Bn, *Cn, *dtb, *Ab, *skipb, *cum, *segsum, *states, *Bx;
    float *rowsum, *expac, *dc, *x2, *gb;
    __half *hh, *ygh, *gbh, *wtin, *wtout, *wtg, *wtu, *wtd;
    cudaGetSymbolAddress((void**)&proj, g_proj);
    cudaGetSymbolAddress((void**)&xg, g_xg);
    cudaGetSymbolAddress((void**)&Bn, g_Bn);
    cudaGetSymbolAddress((void**)&Cn, g_Cn);
    cudaGetSymbolAddress((void**)&dtb, g_dt);
    cudaGetSymbolAddress((void**)&Ab, g_A);
    cudaGetSymbolAddress((void**)&skipb, g_skip);
    cudaGetSymbolAddress((void**)&cum, g_cum);
    cudaGetSymbolAddress((void**)&segsum, g_segsum);
    cudaGetSymbolAddress((void**)&states, g_states);
    cudaGetSymbolAddress((void**)&Bx, g_Bx);
    cudaGetSymbolAddress((void**)&rowsum, g_rowsum);
    cudaGetSymbolAddress((void**)&expac, g_expac);
    cudaGetSymbolAddress((void**)&dc, g_dc);
    cudaGetSymbolAddress((void**)&x2, g_x2);
    cudaGetSymbolAddress((void**)&gb, g_gb);
    cudaGetSymbolAddress((void**)&hh, g_hh);
    cudaGetSymbolAddress((void**)&ygh, g_ygh);
    cudaGetSymbolAddress((void**)&gbh, g_gbh);
    cudaGetSymbolAddress((void**)&wtin, g_Wtin);
    cudaGetSymbolAddress((void**)&wtout, g_Wtout);
    cudaGetSymbolAddress((void**)&wtg, g_Wtg);
    cudaGetSymbolAddress((void**)&wtu, g_Wtu);
    cudaGetSymbolAddress((void**)&wtd, g_Wtd);

    // 0) transpose + fp16 weights -> Wt[n][k] (padded rows zeroed)
    wtransh_kernel<<<dim3(NPAD_IN / 32, DMODEL / 32), 256>>>(W_in, wtin, DMODEL, PROJ);
    wtransh_kernel<<<dim3(DMODEL / 32, DINNER / 32), 256>>>(W_out, wtout, DINNER, DMODEL);
    wtransh_kernel<<<dim3(DMLP / 32, DMODEL / 32), 256>>>(Wg, wtg, DMODEL, DMLP);
    wtransh_kernel<<<dim3(DMLP / 32, DMODEL / 32), 256>>>(Wu, wtu, DMODEL, DMLP);
    wtransh_kernel<<<dim3(DMODEL / 32, DMLP / 32), 256>>>(Wd, wtd, DMLP, DMODEL);

    // 1) hh = rmsnorm(x) (half)
    rmsnorm_kernel<<<TOKENS, 256>>>(x, n1w, hh);
    // 2) proj = hh @ W_in
    hgemm_kernel<<<dim3(NPAD_IN / 128, TOKENS / 128), 256>>>(hh, wtin, nullptr, proj, nullptr,
                                                             TOKENS, PROJ, DMODEL, 0, 1.f);
    // 3) per-token preprocessing
    preproc_kernel<<<TOKENS, 256>>>(proj, A_log, Dp, dtbias, Bbias, Cbias, Bnw, Cnw, xg, Bn,
                                    Cn, dtb, Ab, skipb);
    // 4) cumtheta scan + fused RoPE
    theta_scan1<<<2 * NHEADS * 8, 1024>>>(proj, dtb, cum, segsum);
    theta_rope_kernel<<<2 * NHEADS * 8, 1024>>>(cum, segsum, Bn, Cn);
    // 5) per-chunk states/Bx + decay scalars
    ssd_chunk_kernel<<<2 * NHEADS * NCHUNK, 256>>>(xg, Bn, Ab, states, Bx, rowsum, expac, dc);
    // 6) inter-chunk scan
    ssd_scan_kernel<<<2 * NHEADS * 4, 256>>>(states, dc);
    // 7) Y + skip + silu(z) gate -> ygh = half(y/64)
    ssd_y_kernel<<<2 * NHEADS * NCHUNK, 256>>>(Cn, Bx, states, rowsum, expac, skipb, proj,
                                               ygh);
    // 8) x2 = x + 64*(ygh @ W_out)   (undo the pow2 downscale exactly)
    hgemm_kernel<<<dim3(DMODEL / 128, TOKENS / 128), 256>>>(ygh, wtout, x, x2, nullptr,
                                                            TOKENS, DMODEL, DINNER, 1,
                                                            YUNSCALE);
    // 9) hh = rmsnorm(x2) (half, reuse)
    rmsnorm_kernel<<<TOKENS, 256>>>(x2, n2w, hh);
    // 10) gb = hh @ Wg (float)
    hgemm_kernel<<<dim3(DMLP / 128, TOKENS / 128), 256>>>(hh, wtg, nullptr, gb, nullptr,
                                                          TOKENS, DMLP, DMODEL, 0, 1.f);
    // 11) gbh = half(silu(gb) * (hh @ Wu))
    hgemm_kernel<<<dim3(DMLP / 128, TOKENS / 128), 256>>>(hh, wtu, gb, nullptr, gbh, TOKENS,
                                                          DMLP, DMODEL, 2, 1.f);
    // 12) out = x2 + gbh @ Wd
    hgemm_kernel<<<dim3(DMODEL / 128, TOKENS / 128), 256>>>(gbh, wtd, x2, out, nullptr,
                                                            TOKENS, DMODEL, DMLP, 1, 1.f);
}

// round 12
// speedup vs baseline: 4.9039x; 1.0378x over previous
#include <cuda_runtime.h>
#include <cuda_fp16.h>
#include <mma.h>
#include <math.h>
#include <stdint.h>

using namespace nvcuda;

#define TOKENS   8192
#define SEQLEN   4096
#define DMODEL   1024
#define DINNER   2048
#define NHEADS   32
#define HEADDIM  64
#define DSTATE   64
#define CHUNKL   64
#define NCHUNK   64
#define DMLP     2560
#define PROJ     9248
#define NPAD_IN  9472
#define XS_OFF   2048
#define B_OFF    4096
#define C_OFF    6144
#define DT_OFF   8192
#define TH_OFF   8224
#define YSCALE   0.015625f
#define YUNSCALE 64.0f

// ---------------- scratch (device globals: no allocation allowed) ----------------
__device__ float g_proj[75759616];
__device__ float g_xg[TOKENS * DINNER];
__device__ float g_Bn[TOKENS * DINNER];
__device__ float g_Cn[TOKENS * DINNER];
__device__ float g_dt[TOKENS * NHEADS];
__device__ float g_A[TOKENS * NHEADS];
__device__ float g_skip[TOKENS * NHEADS];
__device__ float g_cum[TOKENS * NHEADS * (DSTATE / 2)];
__device__ float g_segsum[2 * NHEADS * 8 * 32];
__device__ float g_states[2 * NHEADS * NCHUNK * HEADDIM * DSTATE];
__device__ float g_Bx[2 * NHEADS * NCHUNK * HEADDIM * DSTATE];
__device__ float g_rowsum[2 * NHEADS * NCHUNK * CHUNKL];
__device__ float g_expac[2 * NHEADS * NCHUNK * CHUNKL];
__device__ float g_dc[2 * NHEADS * NCHUNK];
__device__ float g_x2[TOKENS * DMODEL];
__device__ float g_gb[TOKENS * DMLP];
__device__ __align__(16) __half g_hh[TOKENS * DMODEL];
__device__ __align__(16) __half g_ygh[TOKENS * DINNER];
__device__ __align__(16) __half g_gbh[TOKENS * DMLP];
__device__ __align__(16) __half g_Wtin[NPAD_IN * DMODEL];
__device__ __align__(16) __half g_Wtout[DMODEL * DINNER];
__device__ __align__(16) __half g_Wtg[DMLP * DMODEL];
__device__ __align__(16) __half g_Wtu[DMLP * DMODEL];
__device__ __align__(16) __half g_Wtd[DMODEL * DMLP];

// ---------------- helpers ----------------
__device__ __forceinline__ void cp16(void* smem, const void* g) {
    uint32_t s = (uint32_t)__cvta_generic_to_shared(smem);
    asm volatile("cp.async.cg.shared.global [%0], [%1], 16;" ::"r"(s), "l"(g));
}

// ---------------- weight transpose + fp16 convert: in[K][N] -> out[Npad][K] ----------------
__global__ __launch_bounds__(256) void wtransh_kernel(const float* __restrict__ in,
                                                      __half* __restrict__ out, int K, int N) {
    __shared__ float tile[32][33];
    int n0 = blockIdx.x * 32, k0 = blockIdx.y * 32;
    int tx = threadIdx.x & 31, ty = threadIdx.x >> 5;
#pragma unroll
    for (int i = ty; i < 32; i += 8) {
        int n = n0 + tx;
        tile[i][tx] = (n < N) ? in[(size_t)(k0 + i) * N + n] : 0.f;
    }
    __syncthreads();
#pragma unroll
    for (int i = ty; i < 32; i += 8)
        out[(size_t)(n0 + i) * K + k0 + tx] = __float2half_rn(tile[tx][i]);
}

// ---------------- FP16 wmma GEMM: C[M,N] = ascale*(A[M,K] @ Bt[n][k]^T) (+epilogue) -----
// BM=BN=128, BK=64, 256 threads, warp grid 2(M)x4(N), warp tile 64x32 (4x2 wmma 16x16x16).
// mode 0: C=v; 1: C=v+Res; 2: Ch = half(silu(Res)*v)     where v = ascale*acc
#define AST 72       // halves per smem row (64 + 8 pad); 144B stride (mult of 16B)
#define HBUF (128 * AST)
#define HG_SMEM (4 * HBUF * 2)  /* 73728 B: 2 stages x (A+B) */
__global__ __launch_bounds__(256, 2) void hgemm_kernel(const __half* __restrict__ A,
                                                       const __half* __restrict__ Bt,
                                                       const float* __restrict__ Res,
                                                       float* __restrict__ C,
                                                       __half* __restrict__ Ch,
                                                       int M, int N, int K, int mode,
                                                       float ascale) {
    extern __shared__ __align__(16) __half smem_h[];
    __half* As0 = smem_h;              // [2][HBUF]
    __half* Bs0 = smem_h + 2 * HBUF;   // [2][HBUF]
    float* stage = (float*)smem_h;     // [64][136] overlay (34816 B < 73728 B)

    int bm = blockIdx.y * 128, bn = blockIdx.x * 128;
    int t = threadIdx.x;
    int warp = t >> 5;
    int wm = warp & 1, wn = warp >> 1;

    // tile: 128 rows x 64 halves = 1024 x 16B chunks per array; 256 thr x 4 = 1024.
    int lrow = t >> 3, lcol = (t & 7) * 8;

    wmma::fragment<wmma::accumulator, 16, 16, 16, float> acc[4][2];
#pragma unroll
    for (int mi = 0; mi < 4; mi++)
#pragma unroll
        for (int nn = 0; nn < 2; nn++) wmma::fill_fragment(acc[mi][nn], 0.f);

    auto issue = [&](int buf, int k0) {
        __half* as = As0 + buf * HBUF;
        __half* bs = Bs0 + buf * HBUF;
#pragma unroll
        for (int r = 0; r < 4; r++) {
            int row = lrow + r * 32;
            cp16(&as[row * AST + lcol], A + (size_t)(bm + row) * K + k0 + lcol);
            cp16(&bs[row * AST + lcol], Bt + (size_t)(bn + row) * K + k0 + lcol);
        }
        asm volatile("cp.async.commit_group;");
    };

    int nk = K / 64;
    issue(0, 0);
    for (int it = 0; it < nk; it++) {
        int buf = it & 1;
        if (it + 1 < nk) {
            issue(buf ^ 1, (it + 1) * 64);
            asm volatile("cp.async.wait_group 1;");
        } else {
            asm volatile("cp.async.wait_group 0;");
        }
        __syncthreads();
        const __half* as = As0 + buf * HBUF;
        const __half* bs = Bs0 + buf * HBUF;
#pragma unroll
        for (int kk = 0; kk < 64; kk += 16) {
            wmma::fragment<wmma::matrix_a, 16, 16, 16, __half, wmma::row_major> af[4];
            wmma::fragment<wmma::matrix_b, 16, 16, 16, __half, wmma::col_major> bf[2];
#pragma unroll
            for (int mi = 0; mi < 4; mi++)
                wmma::load_matrix_sync(af[mi], &as[(wm * 64 + mi * 16) * AST + kk], AST);
#pragma unroll
            for (int nn = 0; nn < 2; nn++)
                wmma::load_matrix_sync(bf[nn], &bs[(wn * 32 + nn * 16) * AST + kk], AST);
#pragma unroll
            for (int mi = 0; mi < 4; mi++)
#pragma unroll
                for (int nn = 0; nn < 2; nn++)
                    wmma::mma_sync(acc[mi][nn], af[mi], bf[nn], acc[mi][nn]);
        }
        __syncthreads();
    }

    // epilogue: two 64-row passes through smem staging (overlays load buffers)
    for (int p = 0; p < 2; p++) {
        __syncthreads();
        if (wm == p) {
#pragma unroll
            for (int mi = 0; mi < 4; mi++)
#pragma unroll
                for (int nn = 0; nn < 2; nn++)
                    wmma::store_matrix_sync(&stage[(mi * 16) * 136 + wn * 32 + nn * 16],
                                            acc[mi][nn], 136, wmma::mem_row_major);
        }
        __syncthreads();
#pragma unroll 4
        for (int u = t; u < 64 * 64; u += 256) {
            int row = u >> 6, c2 = (u & 63) * 2;
            int gc = bn + c2;
            if (gc < N) {
                int gr = bm + p * 64 + row;
                float v0 = stage[row * 136 + c2] * ascale;
                float v1 = stage[row * 136 + c2 + 1] * ascale;
                size_t go = (size_t)gr * N + gc;
                if (mode == 2) {
                    float r0 = Res[go], r1 = Res[go + 1];
                    v0 = r0 / (1.f + __expf(-r0)) * v0;
                    v1 = r1 / (1.f + __expf(-r1)) * v1;
                    *(__half2*)&Ch[go] = __floats2half2_rn(v0, v1);
                } else {
                    if (mode == 1) {
                        v0 += Res[go];
                        v1 += Res[go + 1];
                    }
                    *(float2*)&C[go] = make_float2(v0, v1);
                }
            }
        }
    }
}

// ---------------- rmsnorm over D=1024 (half output) ----------------
__global__ __launch_bounds__(256) void rmsnorm_kernel(const float* __restrict__ x,
                                                      const float* __restrict__ w,
                                                      __half* __restrict__ out) {
    int row = blockIdx.x;
    const float* xr = x + (size_t)row * DMODEL;
    float v[4];
    float s = 0.f;
#pragma unroll
    for (int i = 0; i < 4; i++) {
        v[i] = xr[threadIdx.x + i * 256];
        s += v[i] * v[i];
    }
    __shared__ float red[8];
#pragma unroll
    for (int o = 16; o; o >>= 1) s += __shfl_xor_sync(0xffffffffu, s, o);
    if ((threadIdx.x & 31) == 0) red[threadIdx.x >> 5] = s;
    __syncthreads();
    if (threadIdx.x == 0) {
        float tt = 0.f;
#pragma unroll
        for (int i = 0; i < 8; i++) tt += red[i];
        red[0] = rsqrtf(tt / (float)DMODEL + 1e-5f);
    }
    __syncthreads();
    float r = red[0];
#pragma unroll
    for (int i = 0; i < 4; i++) {
        int c = threadIdx.x + i * 256;
        out[(size_t)row * DMODEL + c] = __float2half_rn(v[i] * r * w[c]);
    }
}

// ---------------- per-token preprocessing ----------------
__global__ __launch_bounds__(256) void preproc_kernel(
    const float* __restrict__ proj, const float* __restrict__ A_log,
    const float* __restrict__ D_param, const float* __restrict__ dt_bias,
    const float* __restrict__ B_bias, const float* __restrict__ C_bias,
    const float* __restrict__ Bn_w, const float* __restrict__ Cn_w,
    float* __restrict__ xg, float* __restrict__ Bn, float* __restrict__ Cn,
    float* __restrict__ dtb, float* __restrict__ Ab, float* __restrict__ skipb) {
    int tok = blockIdx.x;
    const float* p = proj + (size_t)tok * PROJ;
    int warp = threadIdx.x >> 5, lane = threadIdx.x & 31;
    for (int h = warp; h < NHEADS; h += 8) {
        float xb = p[DT_OFF + h] + dt_bias[h];
        float dt = xb > 20.f ? xb : log1pf(expf(xb));
        float Av = -expf(A_log[h]) * dt;
        float alpha = expf(Av);
        float gamma = (alpha - 1.f) / (Av + 1e-6f) * 0.5f + 1.f;
        if (lane == 0) {
            dtb[tok * NHEADS + h] = dt;
            Ab[tok * NHEADS + h] = Av;
        }
        float xs0 = p[XS_OFF + h * 64 + lane];
        float xs1 = p[XS_OFF + h * 64 + 32 + lane];
        float ssum = xs0 + xs1;
#pragma unroll
        for (int o = 16; o; o >>= 1) ssum += __shfl_xor_sync(0xffffffffu, ssum, o);
        if (lane == 0) skipb[tok * NHEADS + h] = D_param[h] * ssum;
        xg[(size_t)tok * DINNER + h * 64 + lane] = xs0 * gamma;
        xg[(size_t)tok * DINNER + h * 64 + 32 + lane] = xs1 * gamma;
        float b0 = p[B_OFF + h * 64 + lane], b1 = p[B_OFF + h * 64 + 32 + lane];
        float bs = b0 * b0 + b1 * b1;
#pragma unroll
        for (int o = 16; o; o >>= 1) bs += __shfl_xor_sync(0xffffffffu, bs, o);
        float br = rsqrtf(bs / 64.f + 1e-5f);
        Bn[(size_t)tok * DINNER + h * 64 + lane] = b0 * br * Bn_w[lane] + B_bias[h * 64 + lane];
        Bn[(size_t)tok * DINNER + h * 64 + 32 + lane] =
            b1 * br * Bn_w[32 + lane] + B_bias[h * 64 + 32 + lane];
        float c0 = p[C_OFF + h * 64 + lane], c1 = p[C_OFF + h * 64 + 32 + lane];
        float cs = c0 * c0 + c1 * c1;
#pragma unroll
        for (int o = 16; o; o >>= 1) cs += __shfl_xor_sync(0xffffffffu, cs, o);
        float cr = rsqrtf(cs / 64.f + 1e-5f);
        Cn[(size_t)tok * DINNER + h * 64 + lane] = c0 * cr * Cn_w[lane] + C_bias[h * 64 + lane];
        Cn[(size_t)tok * DINNER + h * 64 + 32 + lane] =
            c1 * cr * Cn_w[32 + lane] + C_bias[h * 64 + 32 + lane];
    }
}

// ---------------- theta cumsum pass 1 ----------------
__global__ __launch_bounds__(1024) void theta_scan1(const float* __restrict__ proj,
                                                    const float* __restrict__ dtb,
                                                    float* __restrict__ cum,
                                                    float* __restrict__ segsum) {
    int blk = blockIdx.x;
    int seg = blk & 7, h = (blk >> 3) & 31, b = blk >> 8;
    int w = threadIdx.x >> 5, lane = threadIdx.x & 31;
    __shared__ float T[32][33];
    __shared__ float O[32][33];
    __shared__ float Dt[32];
    int s0 = b * SEQLEN + seg * 512;
    float carry = 0.f;
    for (int it = 0; it < 16; it++) {
        int tk = s0 + it * 32;
        T[w][lane] = proj[(size_t)(tk + w) * PROJ + TH_OFF + h * 32 + lane];
        if (w == 0) Dt[lane] = dtb[(tk + lane) * NHEADS + h];
        __syncthreads();
        float v = Dt[lane] * T[lane][w];
#pragma unroll
        for (int o = 1; o < 32; o <<= 1) {
            float tv = __shfl_up_sync(0xffffffffu, v, o);
            if (lane >= o) v += tv;
        }
        v += carry;
        float cnew = __shfl_sync(0xffffffffu, v, 31);
        O[lane][w] = v;
        __syncthreads();
        cum[(size_t)(tk + w) * 1024 + h * 32 + lane] = O[w][lane];
        carry = cnew;
    }
    if (lane == 0) segsum[blk * 32 + w] = carry;
}

// ---------------- pass 2 fused with RoPE ----------------
__global__ __launch_bounds__(1024) void theta_rope_kernel(const float* __restrict__ cum,
                                                          const float* __restrict__ segsum,
                                                          float* __restrict__ Bn,
                                                          float* __restrict__ Cn) {
    int blk = blockIdx.x;
    int seg = blk & 7, h = (blk >> 3) & 31, b = blk >> 8;
    int w = threadIdx.x >> 5, lane = threadIdx.x & 31;
    int bh8 = (b * 32 + h) * 8;
    float off = 0.f;
    for (int s = 0; s < seg; s++) off += segsum[(bh8 + s) * 32 + lane];
    int s0 = b * SEQLEN + seg * 512;
    for (int it = 0; it < 16; it++) {
        int tok = s0 + it * 32 + w;
        float ang = cum[(size_t)tok * 1024 + h * 32 + lane] + off;
        float sn, cs;
        __sincosf(ang, &sn, &cs);
        size_t base = (size_t)tok * DINNER + h * 64 + 2 * lane;
        float2 bv = *(float2*)&Bn[base];
        *(float2*)&Bn[base] = make_float2(cs * bv.x - sn * bv.y, sn * bv.x + cs * bv.y);
        float2 cv = *(float2*)&Cn[base];
        *(float2*)&Cn[base] = make_float2(cs * cv.x - sn * cv.y, sn * cv.x + cs * cv.y);
    }
}

// ---------------- per-chunk: states[n,p], Bx[n,p], decay scalars ----------------
__global__ __launch_bounds__(256) void ssd_chunk_kernel(
    const float* __restrict__ xg, const float* __restrict__ Bn,
    const float* __restrict__ Ab, float* __restrict__ states, float* __restrict__ Bx,
    float* __restrict__ rowsum, float* __restrict__ expac, float* __restrict__ dc) {
    int idx = blockIdx.x;
    int c = idx & 63, h = (idx >> 6) & 31, b = idx >> 11;
    int tokbase = b * SEQLEN + c * 64;
    __shared__ float Xs[64][64];
    __shared__ float Bs[64][64];
    __shared__ float Ac[64];
    __shared__ float decs[64];
    int t = threadIdx.x;
    int lane = t & 31;
    // parallel inclusive cumsum of Ab over 64 tokens: per-warp scan, then offset warp 1
    if (t < 64) {
        float v = Ab[(tokbase + t) * NHEADS + h];
#pragma unroll
        for (int o = 1; o < 32; o <<= 1) {
            float tv = __shfl_up_sync(0xffffffffu, v, o);
            if (lane >= o) v += tv;
        }
        Ac[t] = v;
    }
    __syncthreads();
    if (t >= 32 && t < 64) {
        float base0 = Ac[31];          // read-only here; safe after barrier
        Ac[t] += base0;
    }
    __syncthreads();
    float alast = Ac[63];
    if (t < 64) {
        decs[t] = __expf(alast - Ac[t]);
        expac[(size_t)idx * 64 + t] = __expf(Ac[t]);
        float rs = 64.f - (float)t;
        float act = Ac[t];
        for (int s2 = 0; s2 < t; s2++) rs += __expf(act - Ac[s2]);
        rowsum[(size_t)idx * 64 + t] = rs;
    }
    if (t == 0) dc[idx] = __expf(alast);
    {
        int row = t >> 2, j0 = t & 3;
        const float* xr = xg + (size_t)(tokbase + row) * DINNER + h * 64;
        const float* br = Bn + (size_t)(tokbase + row) * DINNER + h * 64;
#pragma unroll
        for (int j = j0; j < 16; j += 4) {
            *(float4*)&Xs[row][j * 4] = *(const float4*)&xr[j * 4];
            *(float4*)&Bs[row][j * 4] = *(const float4*)&br[j * 4];
        }
    }
    __syncthreads();
    int nt = (t >> 4) * 4, pt = (t & 15) * 4;
    float a1[4][4], a2[4][4];
#pragma unroll
    for (int i = 0; i < 4; i++)
#pragma unroll
        for (int j = 0; j < 4; j++) { a1[i][j] = 0.f; a2[i][j] = 0.f; }
    for (int l = 0; l < 64; l++) {
        float dv = decs[l];
        float bv[4], xv[4];
        *(float4*)bv = *(const float4*)&Bs[l][nt];
        *(float4*)xv = *(const float4*)&Xs[l][pt];
#pragma unroll
        for (int i = 0; i < 4; i++) {
            float bd = bv[i] * dv;
#pragma unroll
            for (int j = 0; j < 4; j++) {
                a1[i][j] += bv[i] * xv[j];
                a2[i][j] += bd * xv[j];
            }
        }
    }
    size_t ob = (size_t)idx * 4096;
#pragma unroll
    for (int i = 0; i < 4; i++) {
        int n = nt + i;
        *(float4*)&Bx[ob + n * 64 + pt] = make_float4(a1[i][0], a1[i][1], a1[i][2], a1[i][3]);
        *(float4*)&states[ob + n * 64 + pt] = make_float4(a2[i][0], a2[i][1], a2[i][2], a2[i][3]);
    }
}

// ---------------- inter-chunk scan ----------------
__global__ __launch_bounds__(256) void ssd_scan_kernel(float* __restrict__ states,
                                                       const float* __restrict__ dc) {
    int bh = blockIdx.x >> 2, slice = blockIdx.x & 3;
    size_t off = (size_t)slice * 1024 + threadIdx.x * 4;
    float4 carry = make_float4(0.f, 0.f, 0.f, 0.f);
    for (int c = 0; c < NCHUNK; c++) {
        size_t base = ((size_t)bh * 64 + c) * 4096 + off;
        float dec = __ldg(&dc[bh * 64 + c]);
        float4 s = *(float4*)&states[base];
        carry.x = carry.x * dec + s.x;
        carry.y = carry.y * dec + s.y;
        carry.z = carry.z * dec + s.z;
        carry.w = carry.w * dec + s.w;
        *(float4*)&states[base] = carry;
    }
}

// ---------------- Y + skip, gated by silu(z) -> yg = half(y_gated/64) ----------------
__global__ __launch_bounds__(256) void ssd_y_kernel(
    const float* __restrict__ Cn, const float* __restrict__ Bx,
    const float* __restrict__ states, const float* __restrict__ rowsum,
    const float* __restrict__ expac, const float* __restrict__ skipb,
    const float* __restrict__ proj, __half* __restrict__ yg) {
    int idx = blockIdx.x;
    int c = idx & 63, h = (idx >> 6) & 31, b = idx >> 11;
    int tokbase = b * SEQLEN + c * 64;
    __shared__ float Ct[64][64];
    __shared__ float Bxs[64][64];
    __shared__ float Ss[64][64];
    int t = threadIdx.x;
    size_t sb = (size_t)idx * 4096;
#pragma unroll
    for (int i = 0; i < 4; i++) {
        int e = i * 1024 + t * 4;
        *(float4*)(&Bxs[0][0] + e) = *(const float4*)&Bx[sb + e];
        *(float4*)(&Ss[0][0] + e) = *(const float4*)&states[sb + e];
    }
    {
        int row = t >> 2, j0 = t & 3;
        const float* cr = Cn + (size_t)(tokbase + row) * DINNER + h * 64;
#pragma unroll
        for (int j = j0; j < 16; j += 4) {
            float4 v = *(const float4*)&cr[j * 4];
            Ct[j * 4 + 0][row] = v.x;
            Ct[j * 4 + 1][row] = v.y;
            Ct[j * 4 + 2][row] = v.z;
            Ct[j * 4 + 3][row] = v.w;
        }
    }
    __syncthreads();
    int lt = (t >> 4) * 4, pt = (t & 15) * 4;
    float p1[4][4], p2[4][4];
#pragma unroll
    for (int i = 0; i < 4; i++)
#pragma unroll
        for (int j = 0; j < 4; j++) { p1[i][j] = 0.f; p2[i][j] = 0.f; }
    for (int n = 0; n < 64; n++) {
        float cv[4], bv[4], sv[4];
        *(float4*)cv = *(const float4*)&Ct[n][lt];
        *(float4*)bv = *(const float4*)&Bxs[n][pt];
        *(float4*)sv = *(const float4*)&Ss[n][pt];
#pragma unroll
        for (int i = 0; i < 4; i++)
#pragma unroll
            for (int j = 0; j < 4; j++) {
                p1[i][j] += cv[i] * bv[j];
                p2[i][j] += cv[i] * sv[j];
            }
    }
#pragma unroll
    for (int i = 0; i < 4; i++) {
        int l = lt + i;
        int tok = tokbase + l;
        float rs = rowsum[(size_t)idx * 64 + l];
        float ea = expac[(size_t)idx * 64 + l];
        float sk = skipb[tok * NHEADS + h];
        float4 z4 = *(const float4*)(proj + (size_t)tok * PROJ + h * 64 + pt);
        float zz[4] = {z4.x, z4.y, z4.z, z4.w};
        float o[4];
#pragma unroll
        for (int j = 0; j < 4; j++) {
            float y = rs * p1[i][j] + ea * p2[i][j] + sk;
            float z = zz[j];
            o[j] = y * (z / (1.f + __expf(-z))) * YSCALE;
        }
        size_t ob = (size_t)tok * DINNER + h * 64 + pt;
        *(__half2*)&yg[ob] = __floats2half2_rn(o[0], o[1]);
        *(__half2*)&yg[ob + 2] = __floats2half2_rn(o[2], o[3]);
    }
}

// ---------------- launch ----------------
extern "C" void kernel_launch(void* const* d_in, const int* in_sizes, int n_in,
                              void* d_out, int out_size) {
    (void)in_sizes; (void)n_in; (void)out_size;
    const float* x = (const float*)d_in[0];
    const float* n1w = (const float*)d_in[1];
    const float* n2w = (const float*)d_in[2];
    const float* W_in = (const float*)d_in[3];
    const float* W_out = (const float*)d_in[4];
    const float* A_log = (const float*)d_in[5];
    const float* Dp = (const float*)d_in[6];
    const float* dtbias = (const float*)d_in[7];
    const float* Bbias = (const float*)d_in[8];
    const float* Cbias = (const float*)d_in[9];
    const float* Bnw = (const float*)d_in[10];
    const float* Cnw = (const float*)d_in[11];
    const float* Wg = (const float*)d_in[12];
    const float* Wu = (const float*)d_in[13];
    const float* Wd = (const float*)d_in[14];
    float* out = (float*)d_out;

    float *proj, *xg, *Bn, *Cn, *dtb, *Ab, *skipb, *cum, *segsum, *states, *Bx;
    float *rowsum, *expac, *dc, *x2, *gb;
    __half *hh, *ygh, *gbh, *wtin, *wtout, *wtg, *wtu, *wtd;
    cudaGetSymbolAddress((void**)&proj, g_proj);
    cudaGetSymbolAddress((void**)&xg, g_xg);
    cudaGetSymbolAddress((void**)&Bn, g_Bn);
    cudaGetSymbolAddress((void**)&Cn, g_Cn);
    cudaGetSymbolAddress((void**)&dtb, g_dt);
    cudaGetSymbolAddress((void**)&Ab, g_A);
    cudaGetSymbolAddress((void**)&skipb, g_skip);
    cudaGetSymbolAddress((void**)&cum, g_cum);
    cudaGetSymbolAddress((void**)&segsum, g_segsum);
    cudaGetSymbolAddress((void**)&states, g_states);
    cudaGetSymbolAddress((void**)&Bx, g_Bx);
    cudaGetSymbolAddress((void**)&rowsum, g_rowsum);
    cudaGetSymbolAddress((void**)&expac, g_expac);
    cudaGetSymbolAddress((void**)&dc, g_dc);
    cudaGetSymbolAddress((void**)&x2, g_x2);
    cudaGetSymbolAddress((void**)&gb, g_gb);
    cudaGetSymbolAddress((void**)&hh, g_hh);
    cudaGetSymbolAddress((void**)&ygh, g_ygh);
    cudaGetSymbolAddress((void**)&gbh, g_gbh);
    cudaGetSymbolAddress((void**)&wtin, g_Wtin);
    cudaGetSymbolAddress((void**)&wtout, g_Wtout);
    cudaGetSymbolAddress((void**)&wtg, g_Wtg);
    cudaGetSymbolAddress((void**)&wtu, g_Wtu);
    cudaGetSymbolAddress((void**)&wtd, g_Wtd);

    static int attr_done = 0;
    if (!attr_done) {
        cudaFuncSetAttribute(hgemm_kernel, cudaFuncAttributeMaxDynamicSharedMemorySize,
                             HG_SMEM);
        attr_done = 1;
    }

    // 0) transpose + fp16 weights -> Wt[n][k] (padded rows zeroed)
    wtransh_kernel<<<dim3(NPAD_IN / 32, DMODEL / 32), 256>>>(W_in, wtin, DMODEL, PROJ);
    wtransh_kernel<<<dim3(DMODEL / 32, DINNER / 32), 256>>>(W_out, wtout, DINNER, DMODEL);
    wtransh_kernel<<<dim3(DMLP / 32, DMODEL / 32), 256>>>(Wg, wtg, DMODEL, DMLP);
    wtransh_kernel<<<dim3(DMLP / 32, DMODEL / 32), 256>>>(Wu, wtu, DMODEL, DMLP);
    wtransh_kernel<<<dim3(DMODEL / 32, DMLP / 32), 256>>>(Wd, wtd, DMLP, DMODEL);

    // 1) hh = rmsnorm(x)
    rmsnorm_kernel<<<TOKENS, 256>>>(x, n1w, hh);
    // 2) proj = hh @ W_in
    hgemm_kernel<<<dim3(NPAD_IN / 128, TOKENS / 128), 256, HG_SMEM>>>(
        hh, wtin, nullptr, proj, nullptr, TOKENS, PROJ, DMODEL, 0, 1.f);
    // 3) per-token preprocessing
    preproc_kernel<<<TOKENS, 256>>>(proj, A_log, Dp, dtbias, Bbias, Cbias, Bnw, Cnw, xg, Bn,
                                    Cn, dtb, Ab, skipb);
    // 4) cumtheta scan + fused RoPE
    theta_scan1<<<2 * NHEADS * 8, 1024>>>(proj, dtb, cum, segsum);
    theta_rope_kernel<<<2 * NHEADS * 8, 1024>>>(cum, segsum, Bn, Cn);
    // 5) per-chunk states/Bx + decay scalars
    ssd_chunk_kernel<<<2 * NHEADS * NCHUNK, 256>>>(xg, Bn, Ab, states, Bx, rowsum, expac, dc);
    // 6) inter-chunk scan
    ssd_scan_kernel<<<2 * NHEADS * 4, 256>>>(states, dc);
    // 7) Y + skip + silu(z) gate -> ygh = half(y/64)
    ssd_y_kernel<<<2 * NHEADS * NCHUNK, 256>>>(Cn, Bx, states, rowsum, expac, skipb, proj,
                                               ygh);
    // 8) x2 = x + 64*(ygh @ W_out)
    hgemm_kernel<<<dim3(DMODEL / 128, TOKENS / 128), 256, HG_SMEM>>>(
        ygh, wtout, x, x2, nullptr, TOKENS, DMODEL, DINNER, 1, YUNSCALE);
    // 9) hh = rmsnorm(x2)
    rmsnorm_kernel<<<TOKENS, 256>>>(x2, n2w, hh);
    // 10) gb = hh @ Wg
    hgemm_kernel<<<dim3(DMLP / 128, TOKENS / 128), 256, HG_SMEM>>>(
        hh, wtg, nullptr, gb, nullptr, TOKENS, DMLP, DMODEL, 0, 1.f);
    // 11) gbh = half(silu(gb) * (hh @ Wu))
    hgemm_kernel<<<dim3(DMLP / 128, TOKENS / 128), 256, HG_SMEM>>>(
        hh, wtu, gb, nullptr, gbh, TOKENS, DMLP, DMODEL, 2, 1.f);
    // 12) out = x2 + gbh @ Wd
    hgemm_kernel<<<dim3(DMODEL / 128, TOKENS / 128), 256, HG_SMEM>>>(
        gbh, wtd, x2, out, nullptr, TOKENS, DMODEL, DMLP, 1, 1.f);
}

// round 13
// speedup vs baseline: 5.1126x; 1.0426x over previous
#include <cuda_runtime.h>
#include <cuda_fp16.h>
#include <mma.h>
#include <math.h>
#include <stdint.h>

using namespace nvcuda;

#define TOKENS   8192
#define SEQLEN   4096
#define DMODEL   1024
#define DINNER   2048
#define NHEADS   32
#define HEADDIM  64
#define DSTATE   64
#define CHUNKL   64
#define NCHUNK   64
#define DMLP     2560
#define PROJ     9248
#define NPAD_IN  9472
#define XS_OFF   2048
#define B_OFF    4096
#define C_OFF    6144
#define DT_OFF   8192
#define TH_OFF   8224
#define YSCALE   0.015625f
#define YUNSCALE 64.0f

// ---------------- scratch (device globals: no allocation allowed) ----------------
__device__ float g_proj[75759616];
__device__ float g_xg[TOKENS * DINNER];
__device__ float g_Bn[TOKENS * DINNER];
__device__ float g_Cn[TOKENS * DINNER];
__device__ float g_dt[TOKENS * NHEADS];
__device__ float g_A[TOKENS * NHEADS];
__device__ float g_skip[TOKENS * NHEADS];
__device__ float g_cum[TOKENS * NHEADS * (DSTATE / 2)];
__device__ float g_segsum[2 * NHEADS * 8 * 32];
__device__ float g_states[2 * NHEADS * NCHUNK * HEADDIM * DSTATE];
__device__ float g_Bx[2 * NHEADS * NCHUNK * HEADDIM * DSTATE];
__device__ float g_rowsum[2 * NHEADS * NCHUNK * CHUNKL];
__device__ float g_expac[2 * NHEADS * NCHUNK * CHUNKL];
__device__ float g_dc[2 * NHEADS * NCHUNK];
__device__ float g_x2[TOKENS * DMODEL];
__device__ float g_gb[TOKENS * DMLP];
__device__ __align__(16) __half g_hh[TOKENS * DMODEL];
__device__ __align__(16) __half g_ygh[TOKENS * DINNER];
__device__ __align__(16) __half g_gbh[TOKENS * DMLP];
__device__ __align__(16) __half g_Wtin[NPAD_IN * DMODEL];
__device__ __align__(16) __half g_Wtout[DMODEL * DINNER];
__device__ __align__(16) __half g_Wtg[DMLP * DMODEL];
__device__ __align__(16) __half g_Wtu[DMLP * DMODEL];
__device__ __align__(16) __half g_Wtd[DMODEL * DMLP];

// ---------------- helpers ----------------
__device__ __forceinline__ void cp16(void* smem, const void* g) {
    uint32_t s = (uint32_t)__cvta_generic_to_shared(smem);
    asm volatile("cp.async.cg.shared.global [%0], [%1], 16;" ::"r"(s), "l"(g));
}

// ---------------- weight transpose + fp16 convert: in[K][N] -> out[Npad][K] ----------------
__global__ __launch_bounds__(256) void wtransh_kernel(const float* __restrict__ in,
                                                      __half* __restrict__ out, int K, int N) {
    __shared__ float tile[32][33];
    int n0 = blockIdx.x * 32, k0 = blockIdx.y * 32;
    int tx = threadIdx.x & 31, ty = threadIdx.x >> 5;
#pragma unroll
    for (int i = ty; i < 32; i += 8) {
        int n = n0 + tx;
        tile[i][tx] = (n < N) ? in[(size_t)(k0 + i) * N + n] : 0.f;
    }
    __syncthreads();
#pragma unroll
    for (int i = ty; i < 32; i += 8)
        out[(size_t)(n0 + i) * K + k0 + tx] = __float2half_rn(tile[tx][i]);
}

// ---------------- FP16 wmma GEMM (unchanged from R12) ----------------
#define AST 72
#define HBUF (128 * AST)
#define HG_SMEM (4 * HBUF * 2)
__global__ __launch_bounds__(256, 2) void hgemm_kernel(const __half* __restrict__ A,
                                                       const __half* __restrict__ Bt,
                                                       const float* __restrict__ Res,
                                                       float* __restrict__ C,
                                                       __half* __restrict__ Ch,
                                                       int M, int N, int K, int mode,
                                                       float ascale) {
    extern __shared__ __align__(16) __half smem_h[];
    __half* As0 = smem_h;
    __half* Bs0 = smem_h + 2 * HBUF;
    float* stage = (float*)smem_h;

    int bm = blockIdx.y * 128, bn = blockIdx.x * 128;
    int t = threadIdx.x;
    int warp = t >> 5;
    int wm = warp & 1, wn = warp >> 1;
    int lrow = t >> 3, lcol = (t & 7) * 8;

    wmma::fragment<wmma::accumulator, 16, 16, 16, float> acc[4][2];
#pragma unroll
    for (int mi = 0; mi < 4; mi++)
#pragma unroll
        for (int nn = 0; nn < 2; nn++) wmma::fill_fragment(acc[mi][nn], 0.f);

    auto issue = [&](int buf, int k0) {
        __half* as = As0 + buf * HBUF;
        __half* bs = Bs0 + buf * HBUF;
#pragma unroll
        for (int r = 0; r < 4; r++) {
            int row = lrow + r * 32;
            cp16(&as[row * AST + lcol], A + (size_t)(bm + row) * K + k0 + lcol);
            cp16(&bs[row * AST + lcol], Bt + (size_t)(bn + row) * K + k0 + lcol);
        }
        asm volatile("cp.async.commit_group;");
    };

    int nk = K / 64;
    issue(0, 0);
    for (int it = 0; it < nk; it++) {
        int buf = it & 1;
        if (it + 1 < nk) {
            issue(buf ^ 1, (it + 1) * 64);
            asm volatile("cp.async.wait_group 1;");
        } else {
            asm volatile("cp.async.wait_group 0;");
        }
        __syncthreads();
        const __half* as = As0 + buf * HBUF;
        const __half* bs = Bs0 + buf * HBUF;
#pragma unroll
        for (int kk = 0; kk < 64; kk += 16) {
            wmma::fragment<wmma::matrix_a, 16, 16, 16, __half, wmma::row_major> af[4];
            wmma::fragment<wmma::matrix_b, 16, 16, 16, __half, wmma::col_major> bf[2];
#pragma unroll
            for (int mi = 0; mi < 4; mi++)
                wmma::load_matrix_sync(af[mi], &as[(wm * 64 + mi * 16) * AST + kk], AST);
#pragma unroll
            for (int nn = 0; nn < 2; nn++)
                wmma::load_matrix_sync(bf[nn], &bs[(wn * 32 + nn * 16) * AST + kk], AST);
#pragma unroll
            for (int mi = 0; mi < 4; mi++)
#pragma unroll
                for (int nn = 0; nn < 2; nn++)
                    wmma::mma_sync(acc[mi][nn], af[mi], bf[nn], acc[mi][nn]);
        }
        __syncthreads();
    }

    for (int p = 0; p < 2; p++) {
        __syncthreads();
        if (wm == p) {
#pragma unroll
            for (int mi = 0; mi < 4; mi++)
#pragma unroll
                for (int nn = 0; nn < 2; nn++)
                    wmma::store_matrix_sync(&stage[(mi * 16) * 136 + wn * 32 + nn * 16],
                                            acc[mi][nn], 136, wmma::mem_row_major);
        }
        __syncthreads();
#pragma unroll 4
        for (int u = t; u < 64 * 64; u += 256) {
            int row = u >> 6, c2 = (u & 63) * 2;
            int gc = bn + c2;
            if (gc < N) {
                int gr = bm + p * 64 + row;
                float v0 = stage[row * 136 + c2] * ascale;
                float v1 = stage[row * 136 + c2 + 1] * ascale;
                size_t go = (size_t)gr * N + gc;
                if (mode == 2) {
                    float r0 = Res[go], r1 = Res[go + 1];
                    v0 = r0 / (1.f + __expf(-r0)) * v0;
                    v1 = r1 / (1.f + __expf(-r1)) * v1;
                    *(__half2*)&Ch[go] = __floats2half2_rn(v0, v1);
                } else {
                    if (mode == 1) {
                        v0 += Res[go];
                        v1 += Res[go + 1];
                    }
                    *(float2*)&C[go] = make_float2(v0, v1);
                }
            }
        }
    }
}

// ---------------- rmsnorm over D=1024 (half output) ----------------
__global__ __launch_bounds__(256) void rmsnorm_kernel(const float* __restrict__ x,
                                                      const float* __restrict__ w,
                                                      __half* __restrict__ out) {
    int row = blockIdx.x;
    const float* xr = x + (size_t)row * DMODEL;
    float v[4];
    float s = 0.f;
#pragma unroll
    for (int i = 0; i < 4; i++) {
        v[i] = xr[threadIdx.x + i * 256];
        s += v[i] * v[i];
    }
    __shared__ float red[8];
#pragma unroll
    for (int o = 16; o; o >>= 1) s += __shfl_xor_sync(0xffffffffu, s, o);
    if ((threadIdx.x & 31) == 0) red[threadIdx.x >> 5] = s;
    __syncthreads();
    if (threadIdx.x == 0) {
        float tt = 0.f;
#pragma unroll
        for (int i = 0; i < 8; i++) tt += red[i];
        red[0] = rsqrtf(tt / (float)DMODEL + 1e-5f);
    }
    __syncthreads();
    float r = red[0];
#pragma unroll
    for (int i = 0; i < 4; i++) {
        int c = threadIdx.x + i * 256;
        out[(size_t)row * DMODEL + c] = __float2half_rn(v[i] * r * w[c]);
    }
}

// ---------------- per-token preprocessing ----------------
__global__ __launch_bounds__(256) void preproc_kernel(
    const float* __restrict__ proj, const float* __restrict__ A_log,
    const float* __restrict__ D_param, const float* __restrict__ dt_bias,
    const float* __restrict__ B_bias, const float* __restrict__ C_bias,
    const float* __restrict__ Bn_w, const float* __restrict__ Cn_w,
    float* __restrict__ xg, float* __restrict__ Bn, float* __restrict__ Cn,
    float* __restrict__ dtb, float* __restrict__ Ab, float* __restrict__ skipb) {
    int tok = blockIdx.x;
    const float* p = proj + (size_t)tok * PROJ;
    int warp = threadIdx.x >> 5, lane = threadIdx.x & 31;
    for (int h = warp; h < NHEADS; h += 8) {
        float xb = p[DT_OFF + h] + dt_bias[h];
        float dt = xb > 20.f ? xb : log1pf(expf(xb));
        float Av = -expf(A_log[h]) * dt;
        float alpha = expf(Av);
        float gamma = (alpha - 1.f) / (Av + 1e-6f) * 0.5f + 1.f;
        if (lane == 0) {
            dtb[tok * NHEADS + h] = dt;
            Ab[tok * NHEADS + h] = Av;
        }
        float xs0 = p[XS_OFF + h * 64 + lane];
        float xs1 = p[XS_OFF + h * 64 + 32 + lane];
        float ssum = xs0 + xs1;
#pragma unroll
        for (int o = 16; o; o >>= 1) ssum += __shfl_xor_sync(0xffffffffu, ssum, o);
        if (lane == 0) skipb[tok * NHEADS + h] = D_param[h] * ssum;
        xg[(size_t)tok * DINNER + h * 64 + lane] = xs0 * gamma;
        xg[(size_t)tok * DINNER + h * 64 + 32 + lane] = xs1 * gamma;
        float b0 = p[B_OFF + h * 64 + lane], b1 = p[B_OFF + h * 64 + 32 + lane];
        float bs = b0 * b0 + b1 * b1;
#pragma unroll
        for (int o = 16; o; o >>= 1) bs += __shfl_xor_sync(0xffffffffu, bs, o);
        float br = rsqrtf(bs / 64.f + 1e-5f);
        Bn[(size_t)tok * DINNER + h * 64 + lane] = b0 * br * Bn_w[lane] + B_bias[h * 64 + lane];
        Bn[(size_t)tok * DINNER + h * 64 + 32 + lane] =
            b1 * br * Bn_w[32 + lane] + B_bias[h * 64 + 32 + lane];
        float c0 = p[C_OFF + h * 64 + lane], c1 = p[C_OFF + h * 64 + 32 + lane];
        float cs = c0 * c0 + c1 * c1;
#pragma unroll
        for (int o = 16; o; o >>= 1) cs += __shfl_xor_sync(0xffffffffu, cs, o);
        float cr = rsqrtf(cs / 64.f + 1e-5f);
        Cn[(size_t)tok * DINNER + h * 64 + lane] = c0 * cr * Cn_w[lane] + C_bias[h * 64 + lane];
        Cn[(size_t)tok * DINNER + h * 64 + 32 + lane] =
            c1 * cr * Cn_w[32 + lane] + C_bias[h * 64 + 32 + lane];
    }
}

// ---------------- theta cumsum pass 1 ----------------
__global__ __launch_bounds__(1024) void theta_scan1(const float* __restrict__ proj,
                                                    const float* __restrict__ dtb,
                                                    float* __restrict__ cum,
                                                    float* __restrict__ segsum) {
    int blk = blockIdx.x;
    int seg = blk & 7, h = (blk >> 3) & 31, b = blk >> 8;
    int w = threadIdx.x >> 5, lane = threadIdx.x & 31;
    __shared__ float T[32][33];
    __shared__ float O[32][33];
    __shared__ float Dt[32];
    int s0 = b * SEQLEN + seg * 512;
    float carry = 0.f;
    for (int it = 0; it < 16; it++) {
        int tk = s0 + it * 32;
        T[w][lane] = proj[(size_t)(tk + w) * PROJ + TH_OFF + h * 32 + lane];
        if (w == 0) Dt[lane] = dtb[(tk + lane) * NHEADS + h];
        __syncthreads();
        float v = Dt[lane] * T[lane][w];
#pragma unroll
        for (int o = 1; o < 32; o <<= 1) {
            float tv = __shfl_up_sync(0xffffffffu, v, o);
            if (lane >= o) v += tv;
        }
        v += carry;
        float cnew = __shfl_sync(0xffffffffu, v, 31);
        O[lane][w] = v;
        __syncthreads();
        cum[(size_t)(tk + w) * 1024 + h * 32 + lane] = O[w][lane];
        carry = cnew;
    }
    if (lane == 0) segsum[blk * 32 + w] = carry;
}

// ---------------- pass 2 fused with RoPE ----------------
__global__ __launch_bounds__(1024) void theta_rope_kernel(const float* __restrict__ cum,
                                                          const float* __restrict__ segsum,
                                                          float* __restrict__ Bn,
                                                          float* __restrict__ Cn) {
    int blk = blockIdx.x;
    int seg = blk & 7, h = (blk >> 3) & 31, b = blk >> 8;
    int w = threadIdx.x >> 5, lane = threadIdx.x & 31;
    int bh8 = (b * 32 + h) * 8;
    float off = 0.f;
    for (int s = 0; s < seg; s++) off += segsum[(bh8 + s) * 32 + lane];
    int s0 = b * SEQLEN + seg * 512;
    for (int it = 0; it < 16; it++) {
        int tok = s0 + it * 32 + w;
        float ang = cum[(size_t)tok * 1024 + h * 32 + lane] + off;
        float sn, cs;
        __sincosf(ang, &sn, &cs);
        size_t base = (size_t)tok * DINNER + h * 64 + 2 * lane;
        float2 bv = *(float2*)&Bn[base];
        *(float2*)&Bn[base] = make_float2(cs * bv.x - sn * bv.y, sn * bv.x + cs * bv.y);
        float2 cv = *(float2*)&Cn[base];
        *(float2*)&Cn[base] = make_float2(cs * cv.x - sn * cv.y, sn * cv.x + cs * cv.y);
    }
}

// ---------------- per-chunk via wmma: states[n,p], Bx[n,p], decay scalars ----------------
// states = (B*dec)^T X, Bx = B^T X  (64x64x64, fp16 operands, fp32 accum)
#define CST 72
__global__ __launch_bounds__(256) void ssd_chunk_kernel(
    const float* __restrict__ xg, const float* __restrict__ Bn,
    const float* __restrict__ Ab, float* __restrict__ states, float* __restrict__ Bx,
    float* __restrict__ rowsum, float* __restrict__ expac, float* __restrict__ dc) {
    int idx = blockIdx.x;
    int c = idx & 63, h = (idx >> 6) & 31, b = idx >> 11;
    int tokbase = b * SEQLEN + c * 64;
    __shared__ __align__(16) __half Bh[64 * CST];
    __shared__ __align__(16) __half Bdh[64 * CST];
    __shared__ __align__(16) __half Xh[64 * CST];
    __shared__ float Ac[64];
    __shared__ float decs[64];
    int t = threadIdx.x;
    int lane = t & 31;
    // parallel inclusive cumsum of Ab over 64 tokens
    if (t < 64) {
        float v = Ab[(tokbase + t) * NHEADS + h];
#pragma unroll
        for (int o = 1; o < 32; o <<= 1) {
            float tv = __shfl_up_sync(0xffffffffu, v, o);
            if (lane >= o) v += tv;
        }
        Ac[t] = v;
    }
    __syncthreads();
    if (t >= 32 && t < 64) Ac[t] += Ac[31];
    __syncthreads();
    float alast = Ac[63];
    if (t < 64) {
        decs[t] = __expf(alast - Ac[t]);
        expac[(size_t)idx * 64 + t] = __expf(Ac[t]);
        float rs = 64.f - (float)t;
        float act = Ac[t];
        for (int s2 = 0; s2 < t; s2++) rs += __expf(act - Ac[s2]);
        rowsum[(size_t)idx * 64 + t] = rs;
    }
    if (t == 0) dc[idx] = __expf(alast);
    __syncthreads();
    // fill smem halves: row = l, cols n/p; Bdh = B*dec[l]
    {
        int row = t >> 2, j0 = (t & 3) * 16;
        float dv = decs[row];
        const float* br = Bn + (size_t)(tokbase + row) * DINNER + h * 64;
        const float* xr = xg + (size_t)(tokbase + row) * DINNER + h * 64;
#pragma unroll
        for (int j = j0; j < j0 + 16; j += 4) {
            float4 bv = *(const float4*)&br[j];
            float4 xv = *(const float4*)&xr[j];
            *(__half2*)&Bh[row * CST + j] = __floats2half2_rn(bv.x, bv.y);
            *(__half2*)&Bh[row * CST + j + 2] = __floats2half2_rn(bv.z, bv.w);
            *(__half2*)&Bdh[row * CST + j] = __floats2half2_rn(bv.x * dv, bv.y * dv);
            *(__half2*)&Bdh[row * CST + j + 2] = __floats2half2_rn(bv.z * dv, bv.w * dv);
            *(__half2*)&Xh[row * CST + j] = __floats2half2_rn(xv.x, xv.y);
            *(__half2*)&Xh[row * CST + j + 2] = __floats2half2_rn(xv.z, xv.w);
        }
    }
    __syncthreads();
    // wmma: warps 0-3 -> Bx (A=Bh), warps 4-7 -> states (A=Bdh); ntile = warp&3
    int warp = t >> 5;
    int prod = warp >> 2, ntile = warp & 3;
    const __half* Am = prod ? Bdh : Bh;
    float* Out = (prod ? states : Bx) + (size_t)idx * 4096;
    wmma::fragment<wmma::accumulator, 16, 16, 16, float> acc[4];
#pragma unroll
    for (int pti = 0; pti < 4; pti++) wmma::fill_fragment(acc[pti], 0.f);
#pragma unroll
    for (int kc = 0; kc < 4; kc++) {
        wmma::fragment<wmma::matrix_a, 16, 16, 16, __half, wmma::col_major> af;
        wmma::load_matrix_sync(af, &Am[(kc * 16) * CST + ntile * 16], CST);
#pragma unroll
        for (int pti = 0; pti < 4; pti++) {
            wmma::fragment<wmma::matrix_b, 16, 16, 16, __half, wmma::row_major> bf;
            wmma::load_matrix_sync(bf, &Xh[(kc * 16) * CST + pti * 16], CST);
            wmma::mma_sync(acc[pti], af, bf, acc[pti]);
        }
    }
#pragma unroll
    for (int pti = 0; pti < 4; pti++)
        wmma::store_matrix_sync(&Out[(ntile * 16) * 64 + pti * 16], acc[pti], 64,
                                wmma::mem_row_major);
}

// ---------------- inter-chunk scan ----------------
__global__ __launch_bounds__(256) void ssd_scan_kernel(float* __restrict__ states,
                                                       const float* __restrict__ dc) {
    int bh = blockIdx.x >> 2, slice = blockIdx.x & 3;
    size_t off = (size_t)slice * 1024 + threadIdx.x * 4;
    float4 carry = make_float4(0.f, 0.f, 0.f, 0.f);
    for (int c = 0; c < NCHUNK; c++) {
        size_t base = ((size_t)bh * 64 + c) * 4096 + off;
        float dec = __ldg(&dc[bh * 64 + c]);
        float4 s = *(float4*)&states[base];
        carry.x = carry.x * dec + s.x;
        carry.y = carry.y * dec + s.y;
        carry.z = carry.z * dec + s.z;
        carry.w = carry.w * dec + s.w;
        *(float4*)&states[base] = carry;
    }
}

// ---------------- Y via wmma: p1 = C·Bx, p2 = C·S; gate -> yg = half(y/64) ------------
__global__ __launch_bounds__(256) void ssd_y_kernel(
    const float* __restrict__ Cn, const float* __restrict__ Bx,
    const float* __restrict__ states, const float* __restrict__ rowsum,
    const float* __restrict__ expac, const float* __restrict__ skipb,
    const float* __restrict__ proj, __half* __restrict__ yg) {
    int idx = blockIdx.x;
    int c = idx & 63, h = (idx >> 6) & 31, b = idx >> 11;
    int tokbase = b * SEQLEN + c * 64;
    __shared__ __align__(16) __half Ch[64 * CST];
    __shared__ __align__(16) __half Bxh[64 * CST];
    __shared__ __align__(16) __half Sh[64 * CST];
    __shared__ float st1[64 * CST];
    __shared__ float st2[64 * CST];
    int t = threadIdx.x;
    size_t sb = (size_t)idx * 4096;
    {
        int row = t >> 2, j0 = (t & 3) * 16;
        const float* cr = Cn + (size_t)(tokbase + row) * DINNER + h * 64;
        const float* bxr = Bx + sb + row * 64;
        const float* sr = states + sb + row * 64;
#pragma unroll
        for (int j = j0; j < j0 + 16; j += 4) {
            float4 cv = *(const float4*)&cr[j];
            float4 bv = *(const float4*)&bxr[j];
            float4 sv = *(const float4*)&sr[j];
            *(__half2*)&Ch[row * CST + j] = __floats2half2_rn(cv.x, cv.y);
            *(__half2*)&Ch[row * CST + j + 2] = __floats2half2_rn(cv.z, cv.w);
            *(__half2*)&Bxh[row * CST + j] = __floats2half2_rn(bv.x, bv.y);
            *(__half2*)&Bxh[row * CST + j + 2] = __floats2half2_rn(bv.z, bv.w);
            *(__half2*)&Sh[row * CST + j] = __floats2half2_rn(sv.x, sv.y);
            *(__half2*)&Sh[row * CST + j + 2] = __floats2half2_rn(sv.z, sv.w);
        }
    }
    __syncthreads();
    // warps 0-3 -> p1 (B=Bxh) into st1; warps 4-7 -> p2 (B=Sh) into st2; ltile = warp&3
    int warp = t >> 5;
    int prod = warp >> 2, ltile = warp & 3;
    const __half* Bm = prod ? Sh : Bxh;
    float* St = prod ? st2 : st1;
    wmma::fragment<wmma::accumulator, 16, 16, 16, float> acc[4];
#pragma unroll
    for (int pti = 0; pti < 4; pti++) wmma::fill_fragment(acc[pti], 0.f);
#pragma unroll
    for (int kc = 0; kc < 4; kc++) {
        wmma::fragment<wmma::matrix_a, 16, 16, 16, __half, wmma::row_major> af;
        wmma::load_matrix_sync(af, &Ch[(ltile * 16) * CST + kc * 16], CST);
#pragma unroll
        for (int pti = 0; pti < 4; pti++) {
            wmma::fragment<wmma::matrix_b, 16, 16, 16, __half, wmma::row_major> bf;
            wmma::load_matrix_sync(bf, &Bm[(kc * 16) * CST + pti * 16], CST);
            wmma::mma_sync(acc[pti], af, bf, acc[pti]);
        }
    }
#pragma unroll
    for (int pti = 0; pti < 4; pti++)
        wmma::store_matrix_sync(&St[(ltile * 16) * CST + pti * 16], acc[pti], CST,
                                wmma::mem_row_major);
    __syncthreads();
    // elementwise: y = rs*p1 + ea*p2 + sk, gated by silu(z), scaled, half store
    {
        int l = t >> 2, j0 = (t & 3) * 16;
        int tok = tokbase + l;
        float rs = rowsum[(size_t)idx * 64 + l];
        float ea = expac[(size_t)idx * 64 + l];
        float sk = skipb[tok * NHEADS + h];
        const float* zp = proj + (size_t)tok * PROJ + h * 64;
        __half* yo = yg + (size_t)tok * DINNER + h * 64;
#pragma unroll
        for (int j = j0; j < j0 + 16; j += 4) {
            float4 z4 = *(const float4*)&zp[j];
            float o[4];
            float zz[4] = {z4.x, z4.y, z4.z, z4.w};
#pragma unroll
            for (int q = 0; q < 4; q++) {
                float y = rs * st1[l * CST + j + q] + ea * st2[l * CST + j + q] + sk;
                o[q] = y * (zz[q] / (1.f + __expf(-zz[q]))) * YSCALE;
            }
            *(__half2*)&yo[j] = __floats2half2_rn(o[0], o[1]);
            *(__half2*)&yo[j + 2] = __floats2half2_rn(o[2], o[3]);
        }
    }
}

// ---------------- launch ----------------
extern "C" void kernel_launch(void* const* d_in, const int* in_sizes, int n_in,
                              void* d_out, int out_size) {
    (void)in_sizes; (void)n_in; (void)out_size;
    const float* x = (const float*)d_in[0];
    const float* n1w = (const float*)d_in[1];
    const float* n2w = (const float*)d_in[2];
    const float* W_in = (const float*)d_in[3];
    const float* W_out = (const float*)d_in[4];
    const float* A_log = (const float*)d_in[5];
    const float* Dp = (const float*)d_in[6];
    const float* dtbias = (const float*)d_in[7];
    const float* Bbias = (const float*)d_in[8];
    const float* Cbias = (const float*)d_in[9];
    const float* Bnw = (const float*)d_in[10];
    const float* Cnw = (const float*)d_in[11];
    const float* Wg = (const float*)d_in[12];
    const float* Wu = (const float*)d_in[13];
    const float* Wd = (const float*)d_in[14];
    float* out = (float*)d_out;

    float *proj, *xg, *Bn, *Cn, *dtb, *Ab, *skipb, *cum, *segsum, *states, *Bx;
    float *rowsum, *expac, *dc, *x2, *gb;
    __half *hh, *ygh, *gbh, *wtin, *wtout, *wtg, *wtu, *wtd;
    cudaGetSymbolAddress((void**)&proj, g_proj);
    cudaGetSymbolAddress((void**)&xg, g_xg);
    cudaGetSymbolAddress((void**)&Bn, g_Bn);
    cudaGetSymbolAddress((void**)&Cn, g_Cn);
    cudaGetSymbolAddress((void**)&dtb, g_dt);
    cudaGetSymbolAddress((void**)&Ab, g_A);
    cudaGetSymbolAddress((void**)&skipb, g_skip);
    cudaGetSymbolAddress((void**)&cum, g_cum);
    cudaGetSymbolAddress((void**)&segsum, g_segsum);
    cudaGetSymbolAddress((void**)&states, g_states);
    cudaGetSymbolAddress((void**)&Bx, g_Bx);
    cudaGetSymbolAddress((void**)&rowsum, g_rowsum);
    cudaGetSymbolAddress((void**)&expac, g_expac);
    cudaGetSymbolAddress((void**)&dc, g_dc);
    cudaGetSymbolAddress((void**)&x2, g_x2);
    cudaGetSymbolAddress((void**)&gb, g_gb);
    cudaGetSymbolAddress((void**)&hh, g_hh);
    cudaGetSymbolAddress((void**)&ygh, g_ygh);
    cudaGetSymbolAddress((void**)&gbh, g_gbh);
    cudaGetSymbolAddress((void**)&wtin, g_Wtin);
    cudaGetSymbolAddress((void**)&wtout, g_Wtout);
    cudaGetSymbolAddress((void**)&wtg, g_Wtg);
    cudaGetSymbolAddress((void**)&wtu, g_Wtu);
    cudaGetSymbolAddress((void**)&wtd, g_Wtd);

    static int attr_done = 0;
    if (!attr_done) {
        cudaFuncSetAttribute(hgemm_kernel, cudaFuncAttributeMaxDynamicSharedMemorySize,
                             HG_SMEM);
        attr_done = 1;
    }

    // 0) transpose + fp16 weights
    wtransh_kernel<<<dim3(NPAD_IN / 32, DMODEL / 32), 256>>>(W_in, wtin, DMODEL, PROJ);
    wtransh_kernel<<<dim3(DMODEL / 32, DINNER / 32), 256>>>(W_out, wtout, DINNER, DMODEL);
    wtransh_kernel<<<dim3(DMLP / 32, DMODEL / 32), 256>>>(Wg, wtg, DMODEL, DMLP);
    wtransh_kernel<<<dim3(DMLP / 32, DMODEL / 32), 256>>>(Wu, wtu, DMODEL, DMLP);
    wtransh_kernel<<<dim3(DMODEL / 32, DMLP / 32), 256>>>(Wd, wtd, DMLP, DMODEL);

    // 1) hh = rmsnorm(x)
    rmsnorm_kernel<<<TOKENS, 256>>>(x, n1w, hh);
    // 2) proj = hh @ W_in
    hgemm_kernel<<<dim3(NPAD_IN / 128, TOKENS / 128), 256, HG_SMEM>>>(
        hh, wtin, nullptr, proj, nullptr, TOKENS, PROJ, DMODEL, 0, 1.f);
    // 3) per-token preprocessing
    preproc_kernel<<<TOKENS, 256>>>(proj, A_log, Dp, dtbias, Bbias, Cbias, Bnw, Cnw, xg, Bn,
                                    Cn, dtb, Ab, skipb);
    // 4) cumtheta scan + fused RoPE
    theta_scan1<<<2 * NHEADS * 8, 1024>>>(proj, dtb, cum, segsum);
    theta_rope_kernel<<<2 * NHEADS * 8, 1024>>>(cum, segsum, Bn, Cn);
    // 5) per-chunk states/Bx (wmma) + decay scalars
    ssd_chunk_kernel<<<2 * NHEADS * NCHUNK, 256>>>(xg, Bn, Ab, states, Bx, rowsum, expac, dc);
    // 6) inter-chunk scan
    ssd_scan_kernel<<<2 * NHEADS * 4, 256>>>(states, dc);
    // 7) Y (wmma) + skip + silu(z) gate -> ygh = half(y/64)
    ssd_y_kernel<<<2 * NHEADS * NCHUNK, 256>>>(Cn, Bx, states, rowsum, expac, skipb, proj,
                                               ygh);
    // 8) x2 = x + 64*(ygh @ W_out)
    hgemm_kernel<<<dim3(DMODEL / 128, TOKENS / 128), 256, HG_SMEM>>>(
        ygh, wtout, x, x2, nullptr, TOKENS, DMODEL, DINNER, 1, YUNSCALE);
    // 9) hh = rmsnorm(x2)
    rmsnorm_kernel<<<TOKENS, 256>>>(x2, n2w, hh);
    // 10) gb = hh @ Wg
    hgemm_kernel<<<dim3(DMLP / 128, TOKENS / 128), 256, HG_SMEM>>>(
        hh, wtg, nullptr, gb, nullptr, TOKENS, DMLP, DMODEL, 0, 1.f);
    // 11) gbh = half(silu(gb) * (hh @ Wu))
    hgemm_kernel<<<dim3(DMLP / 128, TOKENS / 128), 256, HG_SMEM>>>(
        hh, wtu, gb, nullptr, gbh, TOKENS, DMLP, DMODEL, 2, 1.f);
    // 12) out = x2 + gbh @ Wd
    hgemm_kernel<<<dim3(DMODEL / 128, TOKENS / 128), 256, HG_SMEM>>>(
        gbh, wtd, x2, out, nullptr, TOKENS, DMODEL, DMLP, 1, 1.f);
}